// round 12
// baseline (speedup 1.0000x reference)
#include <cuda_runtime.h>
#include <cuda_fp16.h>
#include <math.h>
#include <stdint.h>

// ---------------------------------------------------------------------------
// Problem constants
// ---------------------------------------------------------------------------
#define SRC   2048          // S
#define NB    10            // neighbors
#define DDIM  172           // D
#define EDIM  172           // EDGE
#define TDIM  100           // TD
#define EQ    272           // E  = D + TD
#define KD    444           // D + EDGE + TD
#define KDT   4440          // KD * N
#define HD    136           // head dim (E / H)

#define M0    (SRC*NB)      // 20480 rows prop0
#define M1    SRC           // 2048  rows prop1

// output layout offsets (float elements)
#define OUT_R0    0
#define OUT_R1    (SRC*NB*DDIM)
#define OUT_EDGE  (OUT_R1 + SRC*DDIM)
#define OUT_TD    (OUT_EDGE + SRC*NB*EDIM)

// ---------------------------------------------------------------------------
// Scratch (device globals; no allocation allowed)
// ---------------------------------------------------------------------------
__device__ float g_kvp0[M0 * 544];
__device__ float g_qp0 [M0 * EQ];
__device__ float g_kvp1[M1 * 544];
__device__ float g_qp1 [M1 * EQ];

// fp16 mirrors of GEMM operands
__device__ __half hb_emb0 [SRC*NB*NB*DDIM];
__device__ __half hb_edge0[SRC*NB*NB*EDIM];
__device__ __half hb_td0  [SRC*NB*NB*TDIM];
__device__ __half hb_emb1 [SRC*NB*DDIM];
__device__ __half hb_edge1[SRC*NB*EDIM];
__device__ __half hb_td1  [SRC*NB*TDIM];
__device__ __half hb_emb2 [SRC*DDIM];
__device__ __half hb_Wq[EQ*EQ];
__device__ __half hb_Wk[EQ*KDT];
__device__ __half hb_Wv[EQ*KDT];
__device__ __half hb_Wo[EQ*EQ];
__device__ __half hb_W1[DDIM*(EQ+DDIM)];
__device__ __half hb_W2[DDIM*DDIM];
// fp16 intermediates (GEMM-to-GEMM / attention-to-GEMM)
__device__ __half hb_o0[M0*EQ];
__device__ __half hb_a0[M0*EQ];
__device__ __half hb_h0[M0*DDIM];
__device__ __half hb_o1[M1*EQ];
__device__ __half hb_a1[M1*EQ];
__device__ __half hb_h1[M1*DDIM];

// ---------------------------------------------------------------------------
// Fused fp32 -> fp16 conversion over 13 segments (one launch).
// Segment sizes are compile-time constants; offsets in float4 units.
// ---------------------------------------------------------------------------
struct CvtArgs {
    const float* in[13];
    __half*      out[13];
};

// float4-unit segment boundaries (cumulative)
#define C0  0
#define C1  8806400     // emb0  (35,225,600 f)
#define C2  17612800    // edge0
#define C3  22732800    // td0   (20,480,000 f)
#define C4  23613440    // emb1  (3,522,560 f)
#define C5  24494080    // edge1
#define C6  25006080    // td1   (2,048,000 f)
#define C7  25094144    // emb2  (352,256 f)
#define C8  25112640    // Wq    (73,984 f)
#define C9  25414560    // Wk    (1,207,680 f)
#define C10 25716480    // Wv
#define C11 25734976    // Wo    (73,984 f)
#define C12 25754068    // W1    (76,368 f)
#define C13 25761464    // W2    (29,584 f)

__global__ void __launch_bounds__(256)
cvt_all(CvtArgs a)
{
    const int OFF[14] = {C0, C1, C2, C3, C4, C5, C6, C7,
                         C8, C9, C10, C11, C12, C13};
    const int stride = gridDim.x * blockDim.x;
    for (int i = blockIdx.x * blockDim.x + threadIdx.x; i < C13; i += stride) {
        int s = 0;
#pragma unroll
        for (int j = 1; j < 13; j++) s += (i >= OFF[j]);
        int li = i - OFF[s];
        float4 v = reinterpret_cast<const float4*>(a.in[s])[li];
        __half2 h0 = __float22half2_rn(make_float2(v.x, v.y));
        __half2 h1 = __float22half2_rn(make_float2(v.z, v.w));
        uint2 u;
        u.x = *reinterpret_cast<uint32_t*>(&h0);
        u.y = *reinterpret_cast<uint32_t*>(&h1);
        reinterpret_cast<uint2*>(a.out[s])[li] = u;
    }
}

// ---------------------------------------------------------------------------
// A/B gather address functors (fp16, 4-half chunks; all boundaries %4 == 0)
// ---------------------------------------------------------------------------
template<int MODE>
__device__ __forceinline__ const __half* addrA(const __half* __restrict__ A0,
                                               const __half* __restrict__ A1,
                                               const __half* __restrict__ A2,
                                               int lda, int row, int k)
{
    if (MODE == 0) {
        return A0 + (size_t)row * lda + k;
    } else if (MODE == 1) {
        int n2 = k / KD;
        int f  = k - n2 * KD;
        size_t sub = (size_t)row * NB + n2;
        if (f < DDIM)        return A0 + sub * DDIM + f;
        else if (f < 2*DDIM) return A1 + sub * EDIM + (f - DDIM);
        else                 return A2 + sub * TDIM + (f - 2*DDIM);
    } else if (MODE == 2) {
        if (k < DDIM) return A0 + (size_t)row * DDIM + k;
        else          return A1 + (size_t)row * TDIM + (k - DDIM);
    } else { // MODE == 3
        if (k < EQ)   return A0 + (size_t)row * EQ + k;
        else          return A1 + (size_t)row * DDIM + (k - EQ);
    }
}

template<int MODE>
__device__ __forceinline__ const __half* addrB(const __half* __restrict__ B0,
                                               const __half* __restrict__ B1,
                                               int ldb, int n, int k)
{
    if (MODE == 0) return B0 + (size_t)n * ldb + k;
    if (n < EQ)    return B0 + (size_t)n * KDT + k;
    return B1 + (size_t)(n - EQ) * KDT + k;
}

// ---------------------------------------------------------------------------
// PTX helpers
// ---------------------------------------------------------------------------
__device__ __forceinline__ uint32_t smem_u32(const void* p) {
    uint32_t a;
    asm("{ .reg .u64 t; cvta.to.shared.u64 t, %1; cvt.u32.u64 %0, t; }"
        : "=r"(a) : "l"(p));
    return a;
}

__device__ __forceinline__ void cp_async8(uint32_t smem, const void* gmem,
                                          bool valid) {
    int sz = valid ? 8 : 0;
    asm volatile("cp.async.ca.shared.global [%0], [%1], 8, %2;"
                 :: "r"(smem), "l"(gmem), "r"(sz));
}
#define CP_COMMIT() asm volatile("cp.async.commit_group;")
#define CP_WAIT2()  asm volatile("cp.async.wait_group 2;")

__device__ __forceinline__ void ldsm_x4(uint32_t r[4], uint32_t addr) {
    asm volatile("ldmatrix.sync.aligned.m8n8.x4.shared.b16 {%0,%1,%2,%3}, [%4];"
        : "=r"(r[0]), "=r"(r[1]), "=r"(r[2]), "=r"(r[3]) : "r"(addr));
}

__device__ __forceinline__ void mma_f16(float c[4], const uint32_t a[4],
                                        uint32_t b0, uint32_t b1) {
    asm volatile(
        "mma.sync.aligned.m16n8k16.row.col.f32.f16.f16.f32 "
        "{%0,%1,%2,%3}, {%4,%5,%6,%7}, {%8,%9}, {%0,%1,%2,%3};"
        : "+f"(c[0]), "+f"(c[1]), "+f"(c[2]), "+f"(c[3])
        : "r"(a[0]), "r"(a[1]), "r"(a[2]), "r"(a[3]), "r"(b0), "r"(b1));
}

// ---------------------------------------------------------------------------
// mma.sync fp16 GEMM with 4-stage cp.async pipeline + ldmatrix fragments.
//   C[m,n] = act((sum_k A[m,k]*B[n,k] + bias[n]) * alpha)
// CTA tile 128x64xBK32, 256 threads (8 warps, 4x2), warp tile 32x32.
// 4 stages / wait_group 2 -> tolerance of ~2 k-tile periods (> DRAM latency).
// SMEM rows of 32 halves padded to 80 B (conflict-free ldmatrix:
// 5r mod 8 is a permutation).  M %128 == 0, K %4 == 0 hold; N via ZFILL.
// ---------------------------------------------------------------------------
#define STAGES  4
#define ROWB    80
#define A_STG   10240              // 128 * 80
#define B_STG   5120               // 64 * 80
#define B_OFF   (STAGES * A_STG)   // 40960
#define GM_SMEM (B_OFF + STAGES * B_STG)   // 61440

template<int AMODE, int BMODE, bool RELU, bool OUT16>
__global__ void __launch_bounds__(256)
gemm_mma(const __half* __restrict__ A0, const __half* __restrict__ A1,
         const __half* __restrict__ A2, int lda,
         const __half* __restrict__ B0, const __half* __restrict__ B1, int ldb,
         const float* __restrict__ bias0, const float* __restrict__ bias1,
         void* __restrict__ Cv, int M, int N, int K, int ldc, float alpha)
{
    extern __shared__ char sh[];
    const uint32_t sbase = smem_u32(sh);

    const int tid  = threadIdx.x;
    const int wid  = tid >> 5;
    const int lane = tid & 31;
    const int g    = lane >> 2;
    const int t    = lane & 3;
    const int wm   = wid & 3;        // warp m position (0..3) x32 rows
    const int wn   = wid >> 2;       // warp n position (0..1) x32 cols
    const int m0   = blockIdx.y * 128;
    const int n0   = blockIdx.x * 64;

    // ldmatrix per-lane address components (bytes within a stage buffer)
    const uint32_t a_lm = (uint32_t)(wm * 32 + (lane & 7) + ((lane >> 3) & 1) * 8) * ROWB
                        + ((lane >> 4) & 1) * 16;
    const uint32_t b_lm = (uint32_t)(wn * 32 + (lane & 7) + ((lane >> 4) & 1) * 8) * ROWB
                        + ((lane >> 3) & 1) * 16;

    float acc[2][4][4];
#pragma unroll
    for (int i = 0; i < 2; i++)
#pragma unroll
        for (int j = 0; j < 4; j++)
#pragma unroll
            for (int l = 0; l < 4; l++) acc[i][j][l] = 0.f;

    // staging decomposition: thread -> (row group, 4-half chunk)
    const int ar  = tid >> 3;        // rows 0..31 (+32 per step)
    const int akq = tid & 7;         // chunk index within 32-half row
    const int KT  = (K + 31) / 32;

#define ISSUE(st_, k0_)                                                        \
    do {                                                                       \
        const uint32_t abase = sbase + (st_) * A_STG;                          \
        const uint32_t bbase = sbase + B_OFF + (st_) * B_STG;                  \
        const int gk = (k0_) + akq * 4;                                        \
        const bool kval = gk < K;                                              \
        const int gksafe = kval ? gk : 0;                                      \
        _Pragma("unroll")                                                      \
        for (int p = 0; p < 4; p++) {                                          \
            int r = ar + p * 32;                                               \
            const __half* src = addrA<AMODE>(A0, A1, A2, lda, m0 + r, gksafe); \
            cp_async8(abase + r * ROWB + akq * 8, src, kval);                  \
        }                                                                      \
        _Pragma("unroll")                                                      \
        for (int p = 0; p < 2; p++) {                                          \
            int r = ar + p * 32, gn = n0 + r;                                  \
            bool v = kval && (gn < N);                                         \
            const __half* src = addrB<BMODE>(B0, B1, ldb, v ? gn : 0, gksafe); \
            cp_async8(bbase + r * ROWB + akq * 8, src, v);                     \
        }                                                                      \
    } while (0)

    // prologue: stages 0..2 in flight
    ISSUE(0, 0);  CP_COMMIT();
    ISSUE(1, 32); CP_COMMIT();
    ISSUE(2, 64); CP_COMMIT();
    CP_WAIT2();                      // stage 0 ready
    __syncthreads();

    int st = 0;
    for (int it = 0; it < KT; ++it) {
        // issue loads for stage it+3 (overlaps compute below)
        int st3 = st + 3; if (st3 >= STAGES) st3 -= STAGES;
        if (it + 3 < KT) ISSUE(st3, (it + 3) * 32);
        CP_COMMIT();

        // compute on stage st
        const uint32_t Abu = sbase + st * A_STG + a_lm;
        const uint32_t Bbu = sbase + B_OFF + st * B_STG + b_lm;
#pragma unroll
        for (int ks = 0; ks < 2; ks++) {
            uint32_t af[2][4], bq[2][4];
#pragma unroll
            for (int mt = 0; mt < 2; mt++)
                ldsm_x4(af[mt], Abu + mt * (16 * ROWB) + ks * 32);
#pragma unroll
            for (int ntp = 0; ntp < 2; ntp++)
                ldsm_x4(bq[ntp], Bbu + ntp * (16 * ROWB) + ks * 32);
#pragma unroll
            for (int mt = 0; mt < 2; mt++)
#pragma unroll
                for (int ntp = 0; ntp < 2; ntp++) {
                    mma_f16(acc[mt][2*ntp + 0], af[mt], bq[ntp][0], bq[ntp][1]);
                    mma_f16(acc[mt][2*ntp + 1], af[mt], bq[ntp][2], bq[ntp][3]);
                }
        }

        CP_WAIT2();                  // next stage ready
        __syncthreads();
        if (++st >= STAGES) st = 0;
    }

    // ---- epilogue ----
#pragma unroll
    for (int mt = 0; mt < 2; mt++) {
        int row0 = m0 + wm * 32 + mt * 16 + g;
#pragma unroll
        for (int nt = 0; nt < 4; nt++) {
            int col = n0 + wn * 32 + nt * 8 + t * 2;
#pragma unroll
            for (int half_ = 0; half_ < 2; half_++) {
                int gm = row0 + half_ * 8;
                if (gm >= M) continue;
#pragma unroll
                for (int cc = 0; cc < 2; cc++) {
                    int gn = col + cc;
                    if (gn >= N) continue;
                    float bval = (BMODE == 1)
                               ? (gn < EQ ? bias0[gn] : bias1[gn - EQ])
                               : bias0[gn];
                    float v = (acc[mt][nt][half_ * 2 + cc] + bval) * alpha;
                    if (RELU) v = fmaxf(v, 0.f);
                    if (OUT16)
                        ((__half*)Cv)[(size_t)gm * ldc + gn] = __float2half(v);
                    else
                        ((float*)Cv)[(size_t)gm * ldc + gn] = v;
                }
            }
        }
    }
#undef ISSUE
}

// ---------------------------------------------------------------------------
// Attention prop0: per node, 2 heads, 10x10, hd=136.  Emits fp16 o.
// ---------------------------------------------------------------------------
__global__ void __launch_bounds__(256)
attn0_kernel(const float* __restrict__ qp, const float* __restrict__ kvp,
             __half* __restrict__ o)
{
    __shared__ float Qs[NB][EQ];
    __shared__ float Ks[NB][EQ];
    __shared__ float Vs[NB][EQ];
    __shared__ float P[2][NB][NB];

    const int s = blockIdx.x;
    const int tid = threadIdx.x;
    const size_t base = (size_t)s * NB;

    for (int i = tid; i < NB * EQ; i += 256) {
        int r = i / EQ, f = i - r * EQ;
        Qs[r][f] = qp[(base + r) * EQ + f];
        Ks[r][f] = kvp[(base + r) * 544 + f];
        Vs[r][f] = kvp[(base + r) * 544 + EQ + f];
    }
    __syncthreads();

    if (tid < 200) {
        int h = tid / 100, rem = tid - h * 100;
        int qi = rem / NB, ki = rem - qi * NB;
        const float* q = &Qs[qi][h * HD];
        const float* k = &Ks[ki][h * HD];
        float acc = 0.f;
#pragma unroll 8
        for (int d = 0; d < HD; d++) acc = fmaf(q[d], k[d], acc);
        P[h][qi][ki] = acc;
    }
    __syncthreads();

    if (tid < 20) {
        int h = tid / NB, qi = tid - h * NB;
        float mx = -1e30f;
#pragma unroll
        for (int ki = 0; ki < NB; ki++) mx = fmaxf(mx, P[h][qi][ki]);
        float sum = 0.f;
#pragma unroll
        for (int ki = 0; ki < NB; ki++) {
            float e = expf(P[h][qi][ki] - mx);
            P[h][qi][ki] = e;
            sum += e;
        }
        float inv = 1.f / sum;
#pragma unroll
        for (int ki = 0; ki < NB; ki++) P[h][qi][ki] *= inv;
    }
    __syncthreads();

    for (int i = tid; i < NB * EQ; i += 256) {
        int qi = i / EQ, f = i - qi * EQ;
        int h = f / HD;
        float acc = 0.f;
#pragma unroll
        for (int ki = 0; ki < NB; ki++) acc = fmaf(P[h][qi][ki], Vs[ki][f], acc);
        o[(base + qi) * EQ + f] = __float2half(acc);
    }
}

// ---------------------------------------------------------------------------
// Attention prop1: full 2048x2048, flash-style online softmax.  Emits fp16 o.
// ---------------------------------------------------------------------------
#define A1_BQ   32
#define A1_BK   64
#define A1_KP   137
#define A1_PP   65
#define A1_SMEM_FLOATS (A1_BQ*HD + 2*A1_BK*A1_KP + A1_BQ*A1_PP + 3*A1_BQ)

__global__ void __launch_bounds__(256)
attn1_kernel(const float* __restrict__ qp, const float* __restrict__ kvp,
             __half* __restrict__ o)
{
    extern __shared__ float sm[];
    float* Qs = sm;
    float* Ksm = Qs + A1_BQ * HD;
    float* Vsm = Ksm + A1_BK * A1_KP;
    float* Ps  = Vsm + A1_BK * A1_KP;
    float* m_s = Ps + A1_BQ * A1_PP;
    float* l_s = m_s + A1_BQ;
    float* al_s = l_s + A1_BQ;

    const int h  = blockIdx.y;
    const int q0 = blockIdx.x * A1_BQ;
    const int tid = threadIdx.x;

    for (int i = tid; i < A1_BQ * HD; i += 256) {
        int r = i / HD, d = i - r * HD;
        Qs[r * HD + d] = qp[(size_t)(q0 + r) * EQ + h * HD + d];
    }
    if (tid < A1_BQ) { m_s[tid] = -1e30f; l_s[tid] = 0.f; }

    const int qown = tid >> 3;
    const int dg   = tid & 7;
    const int tyq  = tid >> 5;
    const int txk  = tid & 31;

    float oacc[17];
#pragma unroll
    for (int j = 0; j < 17; j++) oacc[j] = 0.f;

    for (int kt = 0; kt < SRC; kt += A1_BK) {
        __syncthreads();
        for (int i = tid; i < A1_BK * HD; i += 256) {
            int r = i / HD, d = i - r * HD;
            Ksm[r * A1_KP + d] = kvp[(size_t)(kt + r) * 544 + h * HD + d];
            Vsm[r * A1_KP + d] = kvp[(size_t)(kt + r) * 544 + EQ + h * HD + d];
        }
        __syncthreads();

        float sc[4][2];
#pragma unroll
        for (int i = 0; i < 4; i++) { sc[i][0] = 0.f; sc[i][1] = 0.f; }
        const float* krow0 = &Ksm[(txk * 2 + 0) * A1_KP];
        const float* krow1 = &Ksm[(txk * 2 + 1) * A1_KP];
#pragma unroll 4
        for (int d = 0; d < HD; d++) {
            float kv0 = krow0[d];
            float kv1 = krow1[d];
#pragma unroll
            for (int i = 0; i < 4; i++) {
                float qv = Qs[(tyq * 4 + i) * HD + d];
                sc[i][0] = fmaf(qv, kv0, sc[i][0]);
                sc[i][1] = fmaf(qv, kv1, sc[i][1]);
            }
        }
#pragma unroll
        for (int i = 0; i < 4; i++) {
            Ps[(tyq * 4 + i) * A1_PP + txk * 2 + 0] = sc[i][0];
            Ps[(tyq * 4 + i) * A1_PP + txk * 2 + 1] = sc[i][1];
        }
        __syncthreads();

        if (tid < A1_BQ) {
            float mx = m_s[tid];
            float* prow = &Ps[tid * A1_PP];
#pragma unroll 8
            for (int j = 0; j < A1_BK; j++) mx = fmaxf(mx, prow[j]);
            float al = expf(m_s[tid] - mx);
            float sum = 0.f;
#pragma unroll 8
            for (int j = 0; j < A1_BK; j++) {
                float e = expf(prow[j] - mx);
                prow[j] = e;
                sum += e;
            }
            l_s[tid] = l_s[tid] * al + sum;
            m_s[tid] = mx;
            al_s[tid] = al;
        }
        __syncthreads();

        float al = al_s[qown];
#pragma unroll
        for (int j = 0; j < 17; j++) oacc[j] *= al;
        const float* prow = &Ps[qown * A1_PP];
#pragma unroll 2
        for (int ki = 0; ki < A1_BK; ki++) {
            float p = prow[ki];
            const float* vrow = &Vsm[ki * A1_KP + dg * 17];
#pragma unroll
            for (int j = 0; j < 17; j++) oacc[j] = fmaf(p, vrow[j], oacc[j]);
        }
    }

    float inv = 1.f / l_s[qown];
#pragma unroll
    for (int j = 0; j < 17; j++)
        o[(size_t)(q0 + qown) * EQ + h * HD + dg * 17 + j] =
            __float2half(oacc[j] * inv);
}

// ---------------------------------------------------------------------------
// Host launch
// ---------------------------------------------------------------------------
extern "C" void kernel_launch(void* const* d_in, const int* in_sizes, int n_in,
                              void* d_out, int out_size)
{
    const float* emb0  = (const float*)d_in[0];
    const float* edge0 = (const float*)d_in[1];
    const float* td0   = (const float*)d_in[2];
    const float* emb1  = (const float*)d_in[3];
    const float* edge1 = (const float*)d_in[4];
    const float* td1   = (const float*)d_in[5];
    const float* emb2  = (const float*)d_in[6];
    const float* Wq    = (const float*)d_in[7];
    const float* bq    = (const float*)d_in[8];
    const float* Wk    = (const float*)d_in[9];
    const float* bk    = (const float*)d_in[10];
    const float* Wv    = (const float*)d_in[11];
    const float* bv    = (const float*)d_in[12];
    const float* Wo    = (const float*)d_in[13];
    const float* bo    = (const float*)d_in[14];
    const float* W1    = (const float*)d_in[15];
    const float* b1    = (const float*)d_in[16];
    const float* W2    = (const float*)d_in[17];
    const float* b2    = (const float*)d_in[18];
    float* out = (float*)d_out;

    float *kvp0, *qp0, *kvp1, *qp1;
    cudaGetSymbolAddress((void**)&kvp0, g_kvp0);
    cudaGetSymbolAddress((void**)&qp0,  g_qp0);
    cudaGetSymbolAddress((void**)&kvp1, g_kvp1);
    cudaGetSymbolAddress((void**)&qp1,  g_qp1);

    __half *he0, *hg0, *ht0, *he1, *hg1, *ht1, *he2;
    __half *hWq, *hWk, *hWv, *hWo, *hW1, *hW2;
    __half *ho0, *ha0, *hh0, *ho1, *ha1, *hh1;
    cudaGetSymbolAddress((void**)&he0, hb_emb0);
    cudaGetSymbolAddress((void**)&hg0, hb_edge0);
    cudaGetSymbolAddress((void**)&ht0, hb_td0);
    cudaGetSymbolAddress((void**)&he1, hb_emb1);
    cudaGetSymbolAddress((void**)&hg1, hb_edge1);
    cudaGetSymbolAddress((void**)&ht1, hb_td1);
    cudaGetSymbolAddress((void**)&he2, hb_emb2);
    cudaGetSymbolAddress((void**)&hWq, hb_Wq);
    cudaGetSymbolAddress((void**)&hWk, hb_Wk);
    cudaGetSymbolAddress((void**)&hWv, hb_Wv);
    cudaGetSymbolAddress((void**)&hWo, hb_Wo);
    cudaGetSymbolAddress((void**)&hW1, hb_W1);
    cudaGetSymbolAddress((void**)&hW2, hb_W2);
    cudaGetSymbolAddress((void**)&ho0, hb_o0);
    cudaGetSymbolAddress((void**)&ha0, hb_a0);
    cudaGetSymbolAddress((void**)&hh0, hb_h0);
    cudaGetSymbolAddress((void**)&ho1, hb_o1);
    cudaGetSymbolAddress((void**)&ha1, hb_a1);
    cudaGetSymbolAddress((void**)&hh1, hb_h1);

    // static side stream + fork/join events (created once on the
    // correctness call, before graph capture; identical work every call)
    static cudaStream_t s2 = nullptr;
    static cudaEvent_t evFork = nullptr, evJoin = nullptr;
    if (s2 == nullptr) {
        cudaStreamCreateWithFlags(&s2, cudaStreamNonBlocking);
        cudaEventCreateWithFlags(&evFork, cudaEventDisableTiming);
        cudaEventCreateWithFlags(&evJoin, cudaEventDisableTiming);
    }
    cudaStream_t s0 = (cudaStream_t)0;   // legacy default (capture) stream

    const float scale = 1.0f / sqrtf((float)HD);
    const int smem1 = A1_SMEM_FLOATS * (int)sizeof(float);
    cudaFuncSetAttribute(attn1_kernel,
                         cudaFuncAttributeMaxDynamicSharedMemorySize, smem1);
    cudaFuncSetAttribute(gemm_mma<1, 1, false, false>,
                         cudaFuncAttributeMaxDynamicSharedMemorySize, GM_SMEM);
    cudaFuncSetAttribute(gemm_mma<2, 0, false, false>,
                         cudaFuncAttributeMaxDynamicSharedMemorySize, GM_SMEM);
    cudaFuncSetAttribute(gemm_mma<0, 0, false, true>,
                         cudaFuncAttributeMaxDynamicSharedMemorySize, GM_SMEM);
    cudaFuncSetAttribute(gemm_mma<3, 0, true, true>,
                         cudaFuncAttributeMaxDynamicSharedMemorySize, GM_SMEM);
    cudaFuncSetAttribute(gemm_mma<0, 0, false, false>,
                         cudaFuncAttributeMaxDynamicSharedMemorySize, GM_SMEM);

    // ---------------- fused fp16 conversion (single launch) -------------
    CvtArgs ca;
    ca.in[0]  = emb0;  ca.out[0]  = he0;
    ca.in[1]  = edge0; ca.out[1]  = hg0;
    ca.in[2]  = td0;   ca.out[2]  = ht0;
    ca.in[3]  = emb1;  ca.out[3]  = he1;
    ca.in[4]  = edge1; ca.out[4]  = hg1;
    ca.in[5]  = td1;   ca.out[5]  = ht1;
    ca.in[6]  = emb2;  ca.out[6]  = he2;
    ca.in[7]  = Wq;    ca.out[7]  = hWq;
    ca.in[8]  = Wk;    ca.out[8]  = hWk;
    ca.in[9]  = Wv;    ca.out[9]  = hWv;
    ca.in[10] = Wo;    ca.out[10] = hWo;
    ca.in[11] = W1;    ca.out[11] = hW1;
    ca.in[12] = W2;    ca.out[12] = hW2;
    cvt_all<<<4736, 256, 0, s0>>>(ca);

    // ---------------- fork ----------------
    cudaEventRecord(evFork, s0);
    cudaStreamWaitEvent(s2, evFork, 0);

    // ---------------- propagation 1 + passthrough (side stream) ---------
    cudaMemcpyAsync(out + OUT_EDGE, edge1,
                    (size_t)SRC * NB * EDIM * sizeof(float),
                    cudaMemcpyDeviceToDevice, s2);
    cudaMemcpyAsync(out + OUT_TD, td1,
                    (size_t)SRC * NB * TDIM * sizeof(float),
                    cudaMemcpyDeviceToDevice, s2);
    gemm_mma<1, 1, false, false><<<dim3(9, 16), 256, GM_SMEM, s2>>>(
        he1, hg1, ht1, 0, hWk, hWv, KDT, bk, bv,
        kvp1, M1, 544, KDT, 544, 1.f);
    gemm_mma<0, 0, false, false><<<dim3(5, 16), 256, GM_SMEM, s2>>>(
        he2, nullptr, nullptr, DDIM, hWq, nullptr, EQ, bq, nullptr,
        qp1, M1, EQ, DDIM, EQ, scale);
    attn1_kernel<<<dim3(SRC / A1_BQ, 2), 256, smem1, s2>>>(qp1, kvp1, ho1);
    gemm_mma<0, 0, false, true><<<dim3(5, 16), 256, GM_SMEM, s2>>>(
        ho1, nullptr, nullptr, EQ, hWo, nullptr, EQ, bo, nullptr,
        ha1, M1, EQ, EQ, EQ, 1.f);
    gemm_mma<3, 0, true, true><<<dim3(3, 16), 256, GM_SMEM, s2>>>(
        ha1, he2, nullptr, 0, hW1, nullptr, EQ + DDIM, b1, nullptr,
        hh1, M1, DDIM, EQ + DDIM, DDIM, 1.f);
    gemm_mma<0, 0, false, false><<<dim3(3, 16), 256, GM_SMEM, s2>>>(
        hh1, nullptr, nullptr, DDIM, hW2, nullptr, DDIM, b2, nullptr,
        out + OUT_R1, M1, DDIM, DDIM, DDIM, 1.f);
    cudaEventRecord(evJoin, s2);

    // ---------------- propagation 0 (main stream) ----------------
    gemm_mma<1, 1, false, false><<<dim3(9, 160), 256, GM_SMEM, s0>>>(
        he0, hg0, ht0, 0, hWk, hWv, KDT, bk, bv,
        kvp0, M0, 544, KDT, 544, 1.f);
    gemm_mma<2, 0, false, false><<<dim3(5, 160), 256, GM_SMEM, s0>>>(
        he1, ht1, nullptr, 0, hWq, nullptr, EQ, bq, nullptr,
        qp0, M0, EQ, EQ, EQ, scale);
    attn0_kernel<<<SRC, 256, 0, s0>>>(qp0, kvp0, ho0);
    gemm_mma<0, 0, false, true><<<dim3(5, 160), 256, GM_SMEM, s0>>>(
        ho0, nullptr, nullptr, EQ, hWo, nullptr, EQ, bo, nullptr,
        ha0, M0, EQ, EQ, EQ, 1.f);
    gemm_mma<3, 0, true, true><<<dim3(3, 160), 256, GM_SMEM, s0>>>(
        ha0, he1, nullptr, 0, hW1, nullptr, EQ + DDIM, b1, nullptr,
        hh0, M0, DDIM, EQ + DDIM, DDIM, 1.f);
    gemm_mma<0, 0, false, false><<<dim3(3, 160), 256, GM_SMEM, s0>>>(
        hh0, nullptr, nullptr, DDIM, hW2, nullptr, DDIM, b2, nullptr,
        out + OUT_R0, M0, DDIM, DDIM, DDIM, 1.f);

    // ---------------- join ----------------
    cudaStreamWaitEvent(s0, evJoin, 0);
}

// round 13
// speedup vs baseline: 1.2326x; 1.2326x over previous
#include <cuda_runtime.h>
#include <cuda_fp16.h>
#include <math.h>
#include <stdint.h>

// ---------------------------------------------------------------------------
// Problem constants
// ---------------------------------------------------------------------------
#define SRC   2048          // S
#define NB    10            // neighbors
#define DDIM  172           // D
#define EDIM  172           // EDGE
#define TDIM  100           // TD
#define EQ    272           // E  = D + TD
#define KD    444           // D + EDGE + TD
#define KDT   4440          // KD * N
#define HD    136           // head dim (E / H)

#define M0    (SRC*NB)      // 20480 rows prop0
#define M1    SRC           // 2048  rows prop1

// output layout offsets (float elements)
#define OUT_R0    0
#define OUT_R1    (SRC*NB*DDIM)
#define OUT_EDGE  (OUT_R1 + SRC*DDIM)
#define OUT_TD    (OUT_EDGE + SRC*NB*EDIM)

// ---------------------------------------------------------------------------
// Scratch (device globals; no allocation allowed)
// ---------------------------------------------------------------------------
__device__ float g_kvp0[M0 * 544];
__device__ float g_qp0 [M0 * EQ];
__device__ float g_kvp1[M1 * 544];
__device__ float g_qp1 [M1 * EQ];

// split-KV attention partials for prop1
#define A1_SPLITS 8
__device__ float g_po[A1_SPLITS * SRC * 2 * HD];
__device__ float g_pm[A1_SPLITS * SRC * 2];
__device__ float g_pl[A1_SPLITS * SRC * 2];

// fp16 mirrors of GEMM operands
__device__ __half hb_emb0 [SRC*NB*NB*DDIM];
__device__ __half hb_edge0[SRC*NB*NB*EDIM];
__device__ __half hb_td0  [SRC*NB*NB*TDIM];
__device__ __half hb_emb1 [SRC*NB*DDIM];
__device__ __half hb_edge1[SRC*NB*EDIM];
__device__ __half hb_td1  [SRC*NB*TDIM];
__device__ __half hb_emb2 [SRC*DDIM];
__device__ __half hb_Wq[EQ*EQ];
__device__ __half hb_Wk[EQ*KDT];
__device__ __half hb_Wv[EQ*KDT];
__device__ __half hb_Wo[EQ*EQ];
__device__ __half hb_W1[DDIM*(EQ+DDIM)];
__device__ __half hb_W2[DDIM*DDIM];
// fp16 intermediates (GEMM-to-GEMM / attention-to-GEMM)
__device__ __half hb_o0[M0*EQ];
__device__ __half hb_a0[M0*EQ];
__device__ __half hb_h0[M0*DDIM];
__device__ __half hb_o1[M1*EQ];
__device__ __half hb_a1[M1*EQ];
__device__ __half hb_h1[M1*DDIM];

// ---------------------------------------------------------------------------
// Fused fp32 -> fp16 conversion over 13 segments (one launch).
// ---------------------------------------------------------------------------
struct CvtArgs {
    const float* in[13];
    __half*      out[13];
};

#define C0  0
#define C1  8806400
#define C2  17612800
#define C3  22732800
#define C4  23613440
#define C5  24494080
#define C6  25006080
#define C7  25094144
#define C8  25112640
#define C9  25414560
#define C10 25716480
#define C11 25734976
#define C12 25754068
#define C13 25761464

__global__ void __launch_bounds__(256)
cvt_all(CvtArgs a)
{
    const int OFF[14] = {C0, C1, C2, C3, C4, C5, C6, C7,
                         C8, C9, C10, C11, C12, C13};
    const int stride = gridDim.x * blockDim.x;
    for (int i = blockIdx.x * blockDim.x + threadIdx.x; i < C13; i += stride) {
        int s = 0;
#pragma unroll
        for (int j = 1; j < 13; j++) s += (i >= OFF[j]);
        int li = i - OFF[s];
        float4 v = reinterpret_cast<const float4*>(a.in[s])[li];
        __half2 h0 = __float22half2_rn(make_float2(v.x, v.y));
        __half2 h1 = __float22half2_rn(make_float2(v.z, v.w));
        uint2 u;
        u.x = *reinterpret_cast<uint32_t*>(&h0);
        u.y = *reinterpret_cast<uint32_t*>(&h1);
        reinterpret_cast<uint2*>(a.out[s])[li] = u;
    }
}

// ---------------------------------------------------------------------------
// A/B gather address functors (fp16, 4-half chunks; all boundaries %4 == 0)
// ---------------------------------------------------------------------------
template<int MODE>
__device__ __forceinline__ const __half* addrA(const __half* __restrict__ A0,
                                               const __half* __restrict__ A1,
                                               const __half* __restrict__ A2,
                                               int lda, int row, int k)
{
    if (MODE == 0) {
        return A0 + (size_t)row * lda + k;
    } else if (MODE == 1) {
        int n2 = k / KD;
        int f  = k - n2 * KD;
        size_t sub = (size_t)row * NB + n2;
        if (f < DDIM)        return A0 + sub * DDIM + f;
        else if (f < 2*DDIM) return A1 + sub * EDIM + (f - DDIM);
        else                 return A2 + sub * TDIM + (f - 2*DDIM);
    } else if (MODE == 2) {
        if (k < DDIM) return A0 + (size_t)row * DDIM + k;
        else          return A1 + (size_t)row * TDIM + (k - DDIM);
    } else { // MODE == 3
        if (k < EQ)   return A0 + (size_t)row * EQ + k;
        else          return A1 + (size_t)row * DDIM + (k - EQ);
    }
}

template<int MODE>
__device__ __forceinline__ const __half* addrB(const __half* __restrict__ B0,
                                               const __half* __restrict__ B1,
                                               int ldb, int n, int k)
{
    if (MODE == 0) return B0 + (size_t)n * ldb + k;
    if (n < EQ)    return B0 + (size_t)n * KDT + k;
    return B1 + (size_t)(n - EQ) * KDT + k;
}

// ---------------------------------------------------------------------------
// PTX helpers
// ---------------------------------------------------------------------------
__device__ __forceinline__ uint32_t smem_u32(const void* p) {
    uint32_t a;
    asm("{ .reg .u64 t; cvta.to.shared.u64 t, %1; cvt.u32.u64 %0, t; }"
        : "=r"(a) : "l"(p));
    return a;
}

__device__ __forceinline__ void cp_async8(uint32_t smem, const void* gmem,
                                          bool valid) {
    int sz = valid ? 8 : 0;
    asm volatile("cp.async.ca.shared.global [%0], [%1], 8, %2;"
                 :: "r"(smem), "l"(gmem), "r"(sz));
}
#define CP_COMMIT() asm volatile("cp.async.commit_group;")
#define CP_WAIT2()  asm volatile("cp.async.wait_group 2;")

__device__ __forceinline__ void ldsm_x4(uint32_t r[4], uint32_t addr) {
    asm volatile("ldmatrix.sync.aligned.m8n8.x4.shared.b16 {%0,%1,%2,%3}, [%4];"
        : "=r"(r[0]), "=r"(r[1]), "=r"(r[2]), "=r"(r[3]) : "r"(addr));
}

__device__ __forceinline__ void mma_f16(float c[4], const uint32_t a[4],
                                        uint32_t b0, uint32_t b1) {
    asm volatile(
        "mma.sync.aligned.m16n8k16.row.col.f32.f16.f16.f32 "
        "{%0,%1,%2,%3}, {%4,%5,%6,%7}, {%8,%9}, {%0,%1,%2,%3};"
        : "+f"(c[0]), "+f"(c[1]), "+f"(c[2]), "+f"(c[3])
        : "r"(a[0]), "r"(a[1]), "r"(a[2]), "r"(a[3]), "r"(b0), "r"(b1));
}

// ---------------------------------------------------------------------------
// mma.sync fp16 GEMM with 4-stage cp.async pipeline + ldmatrix fragments.
// CTA tile 128x64xBK32, 256 threads (8 warps, 4x2), warp tile 32x32.
// ---------------------------------------------------------------------------
#define STAGES  4
#define ROWB    80
#define A_STG   10240
#define B_STG   5120
#define B_OFF   (STAGES * A_STG)
#define GM_SMEM (B_OFF + STAGES * B_STG)   // 61440

template<int AMODE, int BMODE, bool RELU, bool OUT16>
__global__ void __launch_bounds__(256)
gemm_mma(const __half* __restrict__ A0, const __half* __restrict__ A1,
         const __half* __restrict__ A2, int lda,
         const __half* __restrict__ B0, const __half* __restrict__ B1, int ldb,
         const float* __restrict__ bias0, const float* __restrict__ bias1,
         void* __restrict__ Cv, int M, int N, int K, int ldc, float alpha)
{
    extern __shared__ char sh[];
    const uint32_t sbase = smem_u32(sh);

    const int tid  = threadIdx.x;
    const int wid  = tid >> 5;
    const int lane = tid & 31;
    const int g    = lane >> 2;
    const int t    = lane & 3;
    const int wm   = wid & 3;
    const int wn   = wid >> 2;
    const int m0   = blockIdx.y * 128;
    const int n0   = blockIdx.x * 64;

    const uint32_t a_lm = (uint32_t)(wm * 32 + (lane & 7) + ((lane >> 3) & 1) * 8) * ROWB
                        + ((lane >> 4) & 1) * 16;
    const uint32_t b_lm = (uint32_t)(wn * 32 + (lane & 7) + ((lane >> 4) & 1) * 8) * ROWB
                        + ((lane >> 3) & 1) * 16;

    float acc[2][4][4];
#pragma unroll
    for (int i = 0; i < 2; i++)
#pragma unroll
        for (int j = 0; j < 4; j++)
#pragma unroll
            for (int l = 0; l < 4; l++) acc[i][j][l] = 0.f;

    const int ar  = tid >> 3;
    const int akq = tid & 7;
    const int KT  = (K + 31) / 32;

#define ISSUE(st_, k0_)                                                        \
    do {                                                                       \
        const uint32_t abase = sbase + (st_) * A_STG;                          \
        const uint32_t bbase = sbase + B_OFF + (st_) * B_STG;                  \
        const int gk = (k0_) + akq * 4;                                        \
        const bool kval = gk < K;                                              \
        const int gksafe = kval ? gk : 0;                                      \
        _Pragma("unroll")                                                      \
        for (int p = 0; p < 4; p++) {                                          \
            int r = ar + p * 32;                                               \
            const __half* src = addrA<AMODE>(A0, A1, A2, lda, m0 + r, gksafe); \
            cp_async8(abase + r * ROWB + akq * 8, src, kval);                  \
        }                                                                      \
        _Pragma("unroll")                                                      \
        for (int p = 0; p < 2; p++) {                                          \
            int r = ar + p * 32, gn = n0 + r;                                  \
            bool v = kval && (gn < N);                                         \
            const __half* src = addrB<BMODE>(B0, B1, ldb, v ? gn : 0, gksafe); \
            cp_async8(bbase + r * ROWB + akq * 8, src, v);                     \
        }                                                                      \
    } while (0)

    ISSUE(0, 0);  CP_COMMIT();
    ISSUE(1, 32); CP_COMMIT();
    ISSUE(2, 64); CP_COMMIT();
    CP_WAIT2();
    __syncthreads();

    int st = 0;
    for (int it = 0; it < KT; ++it) {
        int st3 = st + 3; if (st3 >= STAGES) st3 -= STAGES;
        if (it + 3 < KT) ISSUE(st3, (it + 3) * 32);
        CP_COMMIT();

        const uint32_t Abu = sbase + st * A_STG + a_lm;
        const uint32_t Bbu = sbase + B_OFF + st * B_STG + b_lm;
#pragma unroll
        for (int ks = 0; ks < 2; ks++) {
            uint32_t af[2][4], bq[2][4];
#pragma unroll
            for (int mt = 0; mt < 2; mt++)
                ldsm_x4(af[mt], Abu + mt * (16 * ROWB) + ks * 32);
#pragma unroll
            for (int ntp = 0; ntp < 2; ntp++)
                ldsm_x4(bq[ntp], Bbu + ntp * (16 * ROWB) + ks * 32);
#pragma unroll
            for (int mt = 0; mt < 2; mt++)
#pragma unroll
                for (int ntp = 0; ntp < 2; ntp++) {
                    mma_f16(acc[mt][2*ntp + 0], af[mt], bq[ntp][0], bq[ntp][1]);
                    mma_f16(acc[mt][2*ntp + 1], af[mt], bq[ntp][2], bq[ntp][3]);
                }
        }

        CP_WAIT2();
        __syncthreads();
        if (++st >= STAGES) st = 0;
    }

#pragma unroll
    for (int mt = 0; mt < 2; mt++) {
        int row0 = m0 + wm * 32 + mt * 16 + g;
#pragma unroll
        for (int nt = 0; nt < 4; nt++) {
            int col = n0 + wn * 32 + nt * 8 + t * 2;
#pragma unroll
            for (int half_ = 0; half_ < 2; half_++) {
                int gm = row0 + half_ * 8;
                if (gm >= M) continue;
#pragma unroll
                for (int cc = 0; cc < 2; cc++) {
                    int gn = col + cc;
                    if (gn >= N) continue;
                    float bval = (BMODE == 1)
                               ? (gn < EQ ? bias0[gn] : bias1[gn - EQ])
                               : bias0[gn];
                    float v = (acc[mt][nt][half_ * 2 + cc] + bval) * alpha;
                    if (RELU) v = fmaxf(v, 0.f);
                    if (OUT16)
                        ((__half*)Cv)[(size_t)gm * ldc + gn] = __float2half(v);
                    else
                        ((float*)Cv)[(size_t)gm * ldc + gn] = v;
                }
            }
        }
    }
#undef ISSUE
}

// ---------------------------------------------------------------------------
// Attention prop0: per node, 2 heads, 10x10, hd=136.  Emits fp16 o.
// ---------------------------------------------------------------------------
__global__ void __launch_bounds__(256)
attn0_kernel(const float* __restrict__ qp, const float* __restrict__ kvp,
             __half* __restrict__ o)
{
    __shared__ float Qs[NB][EQ];
    __shared__ float Ks[NB][EQ];
    __shared__ float Vs[NB][EQ];
    __shared__ float P[2][NB][NB];

    const int s = blockIdx.x;
    const int tid = threadIdx.x;
    const size_t base = (size_t)s * NB;

    for (int i = tid; i < NB * EQ; i += 256) {
        int r = i / EQ, f = i - r * EQ;
        Qs[r][f] = qp[(base + r) * EQ + f];
        Ks[r][f] = kvp[(base + r) * 544 + f];
        Vs[r][f] = kvp[(base + r) * 544 + EQ + f];
    }
    __syncthreads();

    if (tid < 200) {
        int h = tid / 100, rem = tid - h * 100;
        int qi = rem / NB, ki = rem - qi * NB;
        const float* q = &Qs[qi][h * HD];
        const float* k = &Ks[ki][h * HD];
        float acc = 0.f;
#pragma unroll 8
        for (int d = 0; d < HD; d++) acc = fmaf(q[d], k[d], acc);
        P[h][qi][ki] = acc;
    }
    __syncthreads();

    if (tid < 20) {
        int h = tid / NB, qi = tid - h * NB;
        float mx = -1e30f;
#pragma unroll
        for (int ki = 0; ki < NB; ki++) mx = fmaxf(mx, P[h][qi][ki]);
        float sum = 0.f;
#pragma unroll
        for (int ki = 0; ki < NB; ki++) {
            float e = expf(P[h][qi][ki] - mx);
            P[h][qi][ki] = e;
            sum += e;
        }
        float inv = 1.f / sum;
#pragma unroll
        for (int ki = 0; ki < NB; ki++) P[h][qi][ki] *= inv;
    }
    __syncthreads();

    for (int i = tid; i < NB * EQ; i += 256) {
        int qi = i / EQ, f = i - qi * EQ;
        int h = f / HD;
        float acc = 0.f;
#pragma unroll
        for (int ki = 0; ki < NB; ki++) acc = fmaf(P[h][qi][ki], Vs[ki][f], acc);
        o[(base + qi) * EQ + f] = __float2half(acc);
    }
}

// ---------------------------------------------------------------------------
// Attention prop1, split-KV flash:
//   grid (64 q-tiles, 2 heads, 8 splits); each split covers 256 keys.
//   Emits unnormalized partial O + (m, l) per (query, head, split).
// ---------------------------------------------------------------------------
#define A1_BQ   32
#define A1_BK   64
#define A1_KP   137
#define A1_PP   65
#define A1_KVS  (SRC / A1_SPLITS)    // 256 keys per split
#define A1_SMEM_FLOATS (A1_BQ*HD + 2*A1_BK*A1_KP + A1_BQ*A1_PP + 3*A1_BQ)

__global__ void __launch_bounds__(256)
attn1_split_kernel(const float* __restrict__ qp, const float* __restrict__ kvp,
                   float* __restrict__ po, float* __restrict__ pm,
                   float* __restrict__ pl)
{
    extern __shared__ float sm[];
    float* Qs = sm;
    float* Ksm = Qs + A1_BQ * HD;
    float* Vsm = Ksm + A1_BK * A1_KP;
    float* Ps  = Vsm + A1_BK * A1_KP;
    float* m_s = Ps + A1_BQ * A1_PP;
    float* l_s = m_s + A1_BQ;
    float* al_s = l_s + A1_BQ;

    const int h   = blockIdx.y;
    const int q0  = blockIdx.x * A1_BQ;
    const int sp  = blockIdx.z;
    const int kv0 = sp * A1_KVS;
    const int tid = threadIdx.x;

    for (int i = tid; i < A1_BQ * HD; i += 256) {
        int r = i / HD, d = i - r * HD;
        Qs[r * HD + d] = qp[(size_t)(q0 + r) * EQ + h * HD + d];
    }
    if (tid < A1_BQ) { m_s[tid] = -1e30f; l_s[tid] = 0.f; }

    const int qown = tid >> 3;
    const int dg   = tid & 7;
    const int tyq  = tid >> 5;
    const int txk  = tid & 31;

    float oacc[17];
#pragma unroll
    for (int j = 0; j < 17; j++) oacc[j] = 0.f;

    for (int kt = kv0; kt < kv0 + A1_KVS; kt += A1_BK) {
        __syncthreads();
        for (int i = tid; i < A1_BK * HD; i += 256) {
            int r = i / HD, d = i - r * HD;
            Ksm[r * A1_KP + d] = kvp[(size_t)(kt + r) * 544 + h * HD + d];
            Vsm[r * A1_KP + d] = kvp[(size_t)(kt + r) * 544 + EQ + h * HD + d];
        }
        __syncthreads();

        float sc[4][2];
#pragma unroll
        for (int i = 0; i < 4; i++) { sc[i][0] = 0.f; sc[i][1] = 0.f; }
        const float* krow0 = &Ksm[(txk * 2 + 0) * A1_KP];
        const float* krow1 = &Ksm[(txk * 2 + 1) * A1_KP];
#pragma unroll 4
        for (int d = 0; d < HD; d++) {
            float kv0v = krow0[d];
            float kv1v = krow1[d];
#pragma unroll
            for (int i = 0; i < 4; i++) {
                float qv = Qs[(tyq * 4 + i) * HD + d];
                sc[i][0] = fmaf(qv, kv0v, sc[i][0]);
                sc[i][1] = fmaf(qv, kv1v, sc[i][1]);
            }
        }
#pragma unroll
        for (int i = 0; i < 4; i++) {
            Ps[(tyq * 4 + i) * A1_PP + txk * 2 + 0] = sc[i][0];
            Ps[(tyq * 4 + i) * A1_PP + txk * 2 + 1] = sc[i][1];
        }
        __syncthreads();

        if (tid < A1_BQ) {
            float mx = m_s[tid];
            float* prow = &Ps[tid * A1_PP];
#pragma unroll 8
            for (int j = 0; j < A1_BK; j++) mx = fmaxf(mx, prow[j]);
            float al = expf(m_s[tid] - mx);
            float sum = 0.f;
#pragma unroll 8
            for (int j = 0; j < A1_BK; j++) {
                float e = expf(prow[j] - mx);
                prow[j] = e;
                sum += e;
            }
            l_s[tid] = l_s[tid] * al + sum;
            m_s[tid] = mx;
            al_s[tid] = al;
        }
        __syncthreads();

        float al = al_s[qown];
#pragma unroll
        for (int j = 0; j < 17; j++) oacc[j] *= al;
        const float* prow = &Ps[qown * A1_PP];
#pragma unroll 2
        for (int ki = 0; ki < A1_BK; ki++) {
            float p = prow[ki];
            const float* vrow = &Vsm[ki * A1_KP + dg * 17];
#pragma unroll
            for (int j = 0; j < 17; j++) oacc[j] = fmaf(p, vrow[j], oacc[j]);
        }
    }

    // write unnormalized partial O + (m, l)
    const int q = q0 + qown;
    float* podst = &po[(((size_t)sp * SRC + q) * 2 + h) * HD + dg * 17];
#pragma unroll
    for (int j = 0; j < 17; j++) podst[j] = oacc[j];
    if (tid < A1_BQ) {
        size_t idx = ((size_t)sp * SRC + (q0 + tid)) * 2 + h;
        pm[idx] = m_s[tid];
        pl[idx] = l_s[tid];
    }
}

// merge: one block per (query, head); 136 threads over dims
__global__ void __launch_bounds__(160)
attn1_merge_kernel(const float* __restrict__ po, const float* __restrict__ pm,
                   const float* __restrict__ pl, __half* __restrict__ o)
{
    const int q = blockIdx.x;
    const int h = blockIdx.y;
    const int d = threadIdx.x;

    float m[A1_SPLITS], l[A1_SPLITS];
    float M = -1e30f;
#pragma unroll
    for (int s = 0; s < A1_SPLITS; s++) {
        size_t idx = ((size_t)s * SRC + q) * 2 + h;
        m[s] = pm[idx];
        l[s] = pl[idx];
        M = fmaxf(M, m[s]);
    }
    float w[A1_SPLITS];
    float L = 0.f;
#pragma unroll
    for (int s = 0; s < A1_SPLITS; s++) {
        w[s] = expf(m[s] - M);
        L += l[s] * w[s];
    }
    float invL = 1.f / L;

    if (d < HD) {
        float acc = 0.f;
#pragma unroll
        for (int s = 0; s < A1_SPLITS; s++)
            acc = fmaf(po[(((size_t)s * SRC + q) * 2 + h) * HD + d], w[s], acc);
        o[(size_t)q * EQ + h * HD + d] = __float2half(acc * invL);
    }
}

// ---------------------------------------------------------------------------
// Host launch
// ---------------------------------------------------------------------------
extern "C" void kernel_launch(void* const* d_in, const int* in_sizes, int n_in,
                              void* d_out, int out_size)
{
    const float* emb0  = (const float*)d_in[0];
    const float* edge0 = (const float*)d_in[1];
    const float* td0   = (const float*)d_in[2];
    const float* emb1  = (const float*)d_in[3];
    const float* edge1 = (const float*)d_in[4];
    const float* td1   = (const float*)d_in[5];
    const float* emb2  = (const float*)d_in[6];
    const float* Wq    = (const float*)d_in[7];
    const float* bq    = (const float*)d_in[8];
    const float* Wk    = (const float*)d_in[9];
    const float* bk    = (const float*)d_in[10];
    const float* Wv    = (const float*)d_in[11];
    const float* bv    = (const float*)d_in[12];
    const float* Wo    = (const float*)d_in[13];
    const float* bo    = (const float*)d_in[14];
    const float* W1    = (const float*)d_in[15];
    const float* b1    = (const float*)d_in[16];
    const float* W2    = (const float*)d_in[17];
    const float* b2    = (const float*)d_in[18];
    float* out = (float*)d_out;

    float *kvp0, *qp0, *kvp1, *qp1, *po, *pmv, *plv;
    cudaGetSymbolAddress((void**)&kvp0, g_kvp0);
    cudaGetSymbolAddress((void**)&qp0,  g_qp0);
    cudaGetSymbolAddress((void**)&kvp1, g_kvp1);
    cudaGetSymbolAddress((void**)&qp1,  g_qp1);
    cudaGetSymbolAddress((void**)&po,   g_po);
    cudaGetSymbolAddress((void**)&pmv,  g_pm);
    cudaGetSymbolAddress((void**)&plv,  g_pl);

    __half *he0, *hg0, *ht0, *he1, *hg1, *ht1, *he2;
    __half *hWq, *hWk, *hWv, *hWo, *hW1, *hW2;
    __half *ho0, *ha0, *hh0, *ho1, *ha1, *hh1;
    cudaGetSymbolAddress((void**)&he0, hb_emb0);
    cudaGetSymbolAddress((void**)&hg0, hb_edge0);
    cudaGetSymbolAddress((void**)&ht0, hb_td0);
    cudaGetSymbolAddress((void**)&he1, hb_emb1);
    cudaGetSymbolAddress((void**)&hg1, hb_edge1);
    cudaGetSymbolAddress((void**)&ht1, hb_td1);
    cudaGetSymbolAddress((void**)&he2, hb_emb2);
    cudaGetSymbolAddress((void**)&hWq, hb_Wq);
    cudaGetSymbolAddress((void**)&hWk, hb_Wk);
    cudaGetSymbolAddress((void**)&hWv, hb_Wv);
    cudaGetSymbolAddress((void**)&hWo, hb_Wo);
    cudaGetSymbolAddress((void**)&hW1, hb_W1);
    cudaGetSymbolAddress((void**)&hW2, hb_W2);
    cudaGetSymbolAddress((void**)&ho0, hb_o0);
    cudaGetSymbolAddress((void**)&ha0, hb_a0);
    cudaGetSymbolAddress((void**)&hh0, hb_h0);
    cudaGetSymbolAddress((void**)&ho1, hb_o1);
    cudaGetSymbolAddress((void**)&ha1, hb_a1);
    cudaGetSymbolAddress((void**)&hh1, hb_h1);

    static cudaStream_t s2 = nullptr;
    static cudaEvent_t evFork = nullptr, evJoin = nullptr;
    if (s2 == nullptr) {
        cudaStreamCreateWithFlags(&s2, cudaStreamNonBlocking);
        cudaEventCreateWithFlags(&evFork, cudaEventDisableTiming);
        cudaEventCreateWithFlags(&evJoin, cudaEventDisableTiming);
    }
    cudaStream_t s0 = (cudaStream_t)0;

    const float scale = 1.0f / sqrtf((float)HD);
    const int smem1 = A1_SMEM_FLOATS * (int)sizeof(float);
    cudaFuncSetAttribute(attn1_split_kernel,
                         cudaFuncAttributeMaxDynamicSharedMemorySize, smem1);
    cudaFuncSetAttribute(gemm_mma<1, 1, false, false>,
                         cudaFuncAttributeMaxDynamicSharedMemorySize, GM_SMEM);
    cudaFuncSetAttribute(gemm_mma<2, 0, false, false>,
                         cudaFuncAttributeMaxDynamicSharedMemorySize, GM_SMEM);
    cudaFuncSetAttribute(gemm_mma<0, 0, false, true>,
                         cudaFuncAttributeMaxDynamicSharedMemorySize, GM_SMEM);
    cudaFuncSetAttribute(gemm_mma<3, 0, true, true>,
                         cudaFuncAttributeMaxDynamicSharedMemorySize, GM_SMEM);
    cudaFuncSetAttribute(gemm_mma<0, 0, false, false>,
                         cudaFuncAttributeMaxDynamicSharedMemorySize, GM_SMEM);

    // ---------------- fused fp16 conversion (single launch) -------------
    CvtArgs ca;
    ca.in[0]  = emb0;  ca.out[0]  = he0;
    ca.in[1]  = edge0; ca.out[1]  = hg0;
    ca.in[2]  = td0;   ca.out[2]  = ht0;
    ca.in[3]  = emb1;  ca.out[3]  = he1;
    ca.in[4]  = edge1; ca.out[4]  = hg1;
    ca.in[5]  = td1;   ca.out[5]  = ht1;
    ca.in[6]  = emb2;  ca.out[6]  = he2;
    ca.in[7]  = Wq;    ca.out[7]  = hWq;
    ca.in[8]  = Wk;    ca.out[8]  = hWk;
    ca.in[9]  = Wv;    ca.out[9]  = hWv;
    ca.in[10] = Wo;    ca.out[10] = hWo;
    ca.in[11] = W1;    ca.out[11] = hW1;
    ca.in[12] = W2;    ca.out[12] = hW2;
    cvt_all<<<4736, 256, 0, s0>>>(ca);

    // ---------------- fork ----------------
    cudaEventRecord(evFork, s0);
    cudaStreamWaitEvent(s2, evFork, 0);

    // ---------------- propagation 1 + passthrough (side stream) ---------
    cudaMemcpyAsync(out + OUT_EDGE, edge1,
                    (size_t)SRC * NB * EDIM * sizeof(float),
                    cudaMemcpyDeviceToDevice, s2);
    cudaMemcpyAsync(out + OUT_TD, td1,
                    (size_t)SRC * NB * TDIM * sizeof(float),
                    cudaMemcpyDeviceToDevice, s2);
    gemm_mma<1, 1, false, false><<<dim3(9, 16), 256, GM_SMEM, s2>>>(
        he1, hg1, ht1, 0, hWk, hWv, KDT, bk, bv,
        kvp1, M1, 544, KDT, 544, 1.f);
    gemm_mma<0, 0, false, false><<<dim3(5, 16), 256, GM_SMEM, s2>>>(
        he2, nullptr, nullptr, DDIM, hWq, nullptr, EQ, bq, nullptr,
        qp1, M1, EQ, DDIM, EQ, scale);
    attn1_split_kernel<<<dim3(SRC / A1_BQ, 2, A1_SPLITS), 256, smem1, s2>>>(
        qp1, kvp1, po, pmv, plv);
    attn1_merge_kernel<<<dim3(SRC, 2), 160, 0, s2>>>(po, pmv, plv, ho1);
    gemm_mma<0, 0, false, true><<<dim3(5, 16), 256, GM_SMEM, s2>>>(
        ho1, nullptr, nullptr, EQ, hWo, nullptr, EQ, bo, nullptr,
        ha1, M1, EQ, EQ, EQ, 1.f);
    gemm_mma<3, 0, true, true><<<dim3(3, 16), 256, GM_SMEM, s2>>>(
        ha1, he2, nullptr, 0, hW1, nullptr, EQ + DDIM, b1, nullptr,
        hh1, M1, DDIM, EQ + DDIM, DDIM, 1.f);
    gemm_mma<0, 0, false, false><<<dim3(3, 16), 256, GM_SMEM, s2>>>(
        hh1, nullptr, nullptr, DDIM, hW2, nullptr, DDIM, b2, nullptr,
        out + OUT_R1, M1, DDIM, DDIM, DDIM, 1.f);
    cudaEventRecord(evJoin, s2);

    // ---------------- propagation 0 (main stream) ----------------
    gemm_mma<1, 1, false, false><<<dim3(9, 160), 256, GM_SMEM, s0>>>(
        he0, hg0, ht0, 0, hWk, hWv, KDT, bk, bv,
        kvp0, M0, 544, KDT, 544, 1.f);
    gemm_mma<2, 0, false, false><<<dim3(5, 160), 256, GM_SMEM, s0>>>(
        he1, ht1, nullptr, 0, hWq, nullptr, EQ, bq, nullptr,
        qp0, M0, EQ, EQ, EQ, scale);
    attn0_kernel<<<SRC, 256, 0, s0>>>(qp0, kvp0, ho0);
    gemm_mma<0, 0, false, true><<<dim3(5, 160), 256, GM_SMEM, s0>>>(
        ho0, nullptr, nullptr, EQ, hWo, nullptr, EQ, bo, nullptr,
        ha0, M0, EQ, EQ, EQ, 1.f);
    gemm_mma<3, 0, true, true><<<dim3(3, 160), 256, GM_SMEM, s0>>>(
        ha0, he1, nullptr, 0, hW1, nullptr, EQ + DDIM, b1, nullptr,
        hh0, M0, DDIM, EQ + DDIM, DDIM, 1.f);
    gemm_mma<0, 0, false, false><<<dim3(3, 160), 256, GM_SMEM, s0>>>(
        hh0, nullptr, nullptr, DDIM, hW2, nullptr, DDIM, b2, nullptr,
        out + OUT_R0, M0, DDIM, DDIM, DDIM, 1.f);

    // ---------------- join ----------------
    cudaStreamWaitEvent(s0, evJoin, 0);
}

// round 14
// speedup vs baseline: 1.5857x; 1.2865x over previous
#include <cuda_runtime.h>
#include <cuda_fp16.h>
#include <math.h>
#include <stdint.h>

// ---------------------------------------------------------------------------
// Problem constants
// ---------------------------------------------------------------------------
#define SRC   2048          // S
#define NB    10            // neighbors
#define DDIM  172           // D
#define EDIM  172           // EDGE
#define TDIM  100           // TD
#define EQ    272           // E  = D + TD
#define KD    444           // D + EDGE + TD
#define KDT   4440          // KD * N
#define HD    136           // head dim (E / H)

#define M0    (SRC*NB)      // 20480 rows prop0
#define M1    SRC           // 2048  rows prop1

// output layout offsets (float elements)
#define OUT_R0    0
#define OUT_R1    (SRC*NB*DDIM)
#define OUT_EDGE  (OUT_R1 + SRC*DDIM)
#define OUT_TD    (OUT_EDGE + SRC*NB*EDIM)

// ---------------------------------------------------------------------------
// Scratch (device globals; no allocation allowed)
// ---------------------------------------------------------------------------
__device__ float g_kvp0[M0 * 544];
__device__ float g_qp0 [M0 * EQ];

// prop1 attention-as-GEMM buffers
__device__ float  g_S [2 * SRC * SRC];        // logits, fp32
__device__ float  g_zb[SRC];                  // zero bias (static zero-init)

// fp16 mirrors of GEMM operands
__device__ __half hb_emb0 [SRC*NB*NB*DDIM];
__device__ __half hb_edge0[SRC*NB*NB*EDIM];
__device__ __half hb_td0  [SRC*NB*NB*TDIM];
__device__ __half hb_emb1 [SRC*NB*DDIM];
__device__ __half hb_edge1[SRC*NB*EDIM];
__device__ __half hb_td1  [SRC*NB*TDIM];
__device__ __half hb_emb2 [SRC*DDIM];
__device__ __half hb_Wq[EQ*EQ];
__device__ __half hb_Wk[EQ*KDT];
__device__ __half hb_Wv[EQ*KDT];
__device__ __half hb_Wo[EQ*EQ];
__device__ __half hb_W1[DDIM*(EQ+DDIM)];
__device__ __half hb_W2[DDIM*DDIM];
// fp16 intermediates
__device__ __half hb_o0[M0*EQ];
__device__ __half hb_a0[M0*EQ];
__device__ __half hb_h0[M0*DDIM];
__device__ __half hb_kvp1[M1*544];
__device__ __half hb_qp1 [M1*EQ];
__device__ __half hb_P  [2 * SRC * SRC];      // softmax probs, fp16
__device__ __half hb_Vt [2 * HD * SRC];       // V transposed per head
__device__ __half hb_o1[M1*EQ];
__device__ __half hb_a1[M1*EQ];
__device__ __half hb_h1[M1*DDIM];

// ---------------------------------------------------------------------------
// Fused fp32 -> fp16 conversion over 13 segments (one launch).
// ---------------------------------------------------------------------------
struct CvtArgs {
    const float* in[13];
    __half*      out[13];
};

#define C0  0
#define C1  8806400
#define C2  17612800
#define C3  22732800
#define C4  23613440
#define C5  24494080
#define C6  25006080
#define C7  25094144
#define C8  25112640
#define C9  25414560
#define C10 25716480
#define C11 25734976
#define C12 25754068
#define C13 25761464

__global__ void __launch_bounds__(256)
cvt_all(CvtArgs a)
{
    const int OFF[14] = {C0, C1, C2, C3, C4, C5, C6, C7,
                         C8, C9, C10, C11, C12, C13};
    const int stride = gridDim.x * blockDim.x;
    for (int i = blockIdx.x * blockDim.x + threadIdx.x; i < C13; i += stride) {
        int s = 0;
#pragma unroll
        for (int j = 1; j < 13; j++) s += (i >= OFF[j]);
        int li = i - OFF[s];
        float4 v = reinterpret_cast<const float4*>(a.in[s])[li];
        __half2 h0 = __float22half2_rn(make_float2(v.x, v.y));
        __half2 h1 = __float22half2_rn(make_float2(v.z, v.w));
        uint2 u;
        u.x = *reinterpret_cast<uint32_t*>(&h0);
        u.y = *reinterpret_cast<uint32_t*>(&h1);
        reinterpret_cast<uint2*>(a.out[s])[li] = u;
    }
}

// ---------------------------------------------------------------------------
// A/B gather address functors (fp16, 4-half chunks; all boundaries %4 == 0)
// ---------------------------------------------------------------------------
template<int MODE>
__device__ __forceinline__ const __half* addrA(const __half* __restrict__ A0,
                                               const __half* __restrict__ A1,
                                               const __half* __restrict__ A2,
                                               int lda, int row, int k)
{
    if (MODE == 0) {
        return A0 + (size_t)row * lda + k;
    } else if (MODE == 1) {
        int n2 = k / KD;
        int f  = k - n2 * KD;
        size_t sub = (size_t)row * NB + n2;
        if (f < DDIM)        return A0 + sub * DDIM + f;
        else if (f < 2*DDIM) return A1 + sub * EDIM + (f - DDIM);
        else                 return A2 + sub * TDIM + (f - 2*DDIM);
    } else if (MODE == 2) {
        if (k < DDIM) return A0 + (size_t)row * DDIM + k;
        else          return A1 + (size_t)row * TDIM + (k - DDIM);
    } else { // MODE == 3
        if (k < EQ)   return A0 + (size_t)row * EQ + k;
        else          return A1 + (size_t)row * DDIM + (k - EQ);
    }
}

template<int MODE>
__device__ __forceinline__ const __half* addrB(const __half* __restrict__ B0,
                                               const __half* __restrict__ B1,
                                               int ldb, int n, int k)
{
    if (MODE == 0) return B0 + (size_t)n * ldb + k;
    if (n < EQ)    return B0 + (size_t)n * KDT + k;
    return B1 + (size_t)(n - EQ) * KDT + k;
}

// ---------------------------------------------------------------------------
// PTX helpers
// ---------------------------------------------------------------------------
__device__ __forceinline__ uint32_t smem_u32(const void* p) {
    uint32_t a;
    asm("{ .reg .u64 t; cvta.to.shared.u64 t, %1; cvt.u32.u64 %0, t; }"
        : "=r"(a) : "l"(p));
    return a;
}

__device__ __forceinline__ void cp_async8(uint32_t smem, const void* gmem,
                                          bool valid) {
    int sz = valid ? 8 : 0;
    asm volatile("cp.async.ca.shared.global [%0], [%1], 8, %2;"
                 :: "r"(smem), "l"(gmem), "r"(sz));
}
#define CP_COMMIT() asm volatile("cp.async.commit_group;")
#define CP_WAIT2()  asm volatile("cp.async.wait_group 2;")

__device__ __forceinline__ void ldsm_x4(uint32_t r[4], uint32_t addr) {
    asm volatile("ldmatrix.sync.aligned.m8n8.x4.shared.b16 {%0,%1,%2,%3}, [%4];"
        : "=r"(r[0]), "=r"(r[1]), "=r"(r[2]), "=r"(r[3]) : "r"(addr));
}

__device__ __forceinline__ void mma_f16(float c[4], const uint32_t a[4],
                                        uint32_t b0, uint32_t b1) {
    asm volatile(
        "mma.sync.aligned.m16n8k16.row.col.f32.f16.f16.f32 "
        "{%0,%1,%2,%3}, {%4,%5,%6,%7}, {%8,%9}, {%0,%1,%2,%3};"
        : "+f"(c[0]), "+f"(c[1]), "+f"(c[2]), "+f"(c[3])
        : "r"(a[0]), "r"(a[1]), "r"(a[2]), "r"(a[3]), "r"(b0), "r"(b1));
}

// ---------------------------------------------------------------------------
// mma.sync fp16 GEMM with 4-stage cp.async pipeline + ldmatrix fragments.
// CTA tile 128x64xBK32, 256 threads (8 warps, 4x2), warp tile 32x32.
// ---------------------------------------------------------------------------
#define STAGES  4
#define ROWB    80
#define A_STG   10240
#define B_STG   5120
#define B_OFF   (STAGES * A_STG)
#define GM_SMEM (B_OFF + STAGES * B_STG)   // 61440

template<int AMODE, int BMODE, bool RELU, bool OUT16>
__global__ void __launch_bounds__(256)
gemm_mma(const __half* __restrict__ A0, const __half* __restrict__ A1,
         const __half* __restrict__ A2, int lda,
         const __half* __restrict__ B0, const __half* __restrict__ B1, int ldb,
         const float* __restrict__ bias0, const float* __restrict__ bias1,
         void* __restrict__ Cv, int M, int N, int K, int ldc, float alpha)
{
    extern __shared__ char sh[];
    const uint32_t sbase = smem_u32(sh);

    const int tid  = threadIdx.x;
    const int wid  = tid >> 5;
    const int lane = tid & 31;
    const int g    = lane >> 2;
    const int t    = lane & 3;
    const int wm   = wid & 3;
    const int wn   = wid >> 2;
    const int m0   = blockIdx.y * 128;
    const int n0   = blockIdx.x * 64;

    const uint32_t a_lm = (uint32_t)(wm * 32 + (lane & 7) + ((lane >> 3) & 1) * 8) * ROWB
                        + ((lane >> 4) & 1) * 16;
    const uint32_t b_lm = (uint32_t)(wn * 32 + (lane & 7) + ((lane >> 4) & 1) * 8) * ROWB
                        + ((lane >> 3) & 1) * 16;

    float acc[2][4][4];
#pragma unroll
    for (int i = 0; i < 2; i++)
#pragma unroll
        for (int j = 0; j < 4; j++)
#pragma unroll
            for (int l = 0; l < 4; l++) acc[i][j][l] = 0.f;

    const int ar  = tid >> 3;
    const int akq = tid & 7;
    const int KT  = (K + 31) / 32;

#define ISSUE(st_, k0_)                                                        \
    do {                                                                       \
        const uint32_t abase = sbase + (st_) * A_STG;                          \
        const uint32_t bbase = sbase + B_OFF + (st_) * B_STG;                  \
        const int gk = (k0_) + akq * 4;                                        \
        const bool kval = gk < K;                                              \
        const int gksafe = kval ? gk : 0;                                      \
        _Pragma("unroll")                                                      \
        for (int p = 0; p < 4; p++) {                                          \
            int r = ar + p * 32;                                               \
            const __half* src = addrA<AMODE>(A0, A1, A2, lda, m0 + r, gksafe); \
            cp_async8(abase + r * ROWB + akq * 8, src, kval);                  \
        }                                                                      \
        _Pragma("unroll")                                                      \
        for (int p = 0; p < 2; p++) {                                          \
            int r = ar + p * 32, gn = n0 + r;                                  \
            bool v = kval && (gn < N);                                         \
            const __half* src = addrB<BMODE>(B0, B1, ldb, v ? gn : 0, gksafe); \
            cp_async8(bbase + r * ROWB + akq * 8, src, v);                     \
        }                                                                      \
    } while (0)

    ISSUE(0, 0);  CP_COMMIT();
    ISSUE(1, 32); CP_COMMIT();
    ISSUE(2, 64); CP_COMMIT();
    CP_WAIT2();
    __syncthreads();

    int st = 0;
    for (int it = 0; it < KT; ++it) {
        int st3 = st + 3; if (st3 >= STAGES) st3 -= STAGES;
        if (it + 3 < KT) ISSUE(st3, (it + 3) * 32);
        CP_COMMIT();

        const uint32_t Abu = sbase + st * A_STG + a_lm;
        const uint32_t Bbu = sbase + B_OFF + st * B_STG + b_lm;
#pragma unroll
        for (int ks = 0; ks < 2; ks++) {
            uint32_t af[2][4], bq[2][4];
#pragma unroll
            for (int mt = 0; mt < 2; mt++)
                ldsm_x4(af[mt], Abu + mt * (16 * ROWB) + ks * 32);
#pragma unroll
            for (int ntp = 0; ntp < 2; ntp++)
                ldsm_x4(bq[ntp], Bbu + ntp * (16 * ROWB) + ks * 32);
#pragma unroll
            for (int mt = 0; mt < 2; mt++)
#pragma unroll
                for (int ntp = 0; ntp < 2; ntp++) {
                    mma_f16(acc[mt][2*ntp + 0], af[mt], bq[ntp][0], bq[ntp][1]);
                    mma_f16(acc[mt][2*ntp + 1], af[mt], bq[ntp][2], bq[ntp][3]);
                }
        }

        CP_WAIT2();
        __syncthreads();
        if (++st >= STAGES) st = 0;
    }

#pragma unroll
    for (int mt = 0; mt < 2; mt++) {
        int row0 = m0 + wm * 32 + mt * 16 + g;
#pragma unroll
        for (int nt = 0; nt < 4; nt++) {
            int col = n0 + wn * 32 + nt * 8 + t * 2;
#pragma unroll
            for (int half_ = 0; half_ < 2; half_++) {
                int gm = row0 + half_ * 8;
                if (gm >= M) continue;
#pragma unroll
                for (int cc = 0; cc < 2; cc++) {
                    int gn = col + cc;
                    if (gn >= N) continue;
                    float bval = (BMODE == 1)
                               ? (gn < EQ ? bias0[gn] : bias1[gn - EQ])
                               : bias0[gn];
                    float v = (acc[mt][nt][half_ * 2 + cc] + bval) * alpha;
                    if (RELU) v = fmaxf(v, 0.f);
                    if (OUT16)
                        ((__half*)Cv)[(size_t)gm * ldc + gn] = __float2half(v);
                    else
                        ((float*)Cv)[(size_t)gm * ldc + gn] = v;
                }
            }
        }
    }
#undef ISSUE
}

// ---------------------------------------------------------------------------
// Attention prop0: per node, 2 heads, 10x10, hd=136.  Emits fp16 o.
// ---------------------------------------------------------------------------
__global__ void __launch_bounds__(256)
attn0_kernel(const float* __restrict__ qp, const float* __restrict__ kvp,
             __half* __restrict__ o)
{
    __shared__ float Qs[NB][EQ];
    __shared__ float Ks[NB][EQ];
    __shared__ float Vs[NB][EQ];
    __shared__ float P[2][NB][NB];

    const int s = blockIdx.x;
    const int tid = threadIdx.x;
    const size_t base = (size_t)s * NB;

    for (int i = tid; i < NB * EQ; i += 256) {
        int r = i / EQ, f = i - r * EQ;
        Qs[r][f] = qp[(base + r) * EQ + f];
        Ks[r][f] = kvp[(base + r) * 544 + f];
        Vs[r][f] = kvp[(base + r) * 544 + EQ + f];
    }
    __syncthreads();

    if (tid < 200) {
        int h = tid / 100, rem = tid - h * 100;
        int qi = rem / NB, ki = rem - qi * NB;
        const float* q = &Qs[qi][h * HD];
        const float* k = &Ks[ki][h * HD];
        float acc = 0.f;
#pragma unroll 8
        for (int d = 0; d < HD; d++) acc = fmaf(q[d], k[d], acc);
        P[h][qi][ki] = acc;
    }
    __syncthreads();

    if (tid < 20) {
        int h = tid / NB, qi = tid - h * NB;
        float mx = -1e30f;
#pragma unroll
        for (int ki = 0; ki < NB; ki++) mx = fmaxf(mx, P[h][qi][ki]);
        float sum = 0.f;
#pragma unroll
        for (int ki = 0; ki < NB; ki++) {
            float e = expf(P[h][qi][ki] - mx);
            P[h][qi][ki] = e;
            sum += e;
        }
        float inv = 1.f / sum;
#pragma unroll
        for (int ki = 0; ki < NB; ki++) P[h][qi][ki] *= inv;
    }
    __syncthreads();

    for (int i = tid; i < NB * EQ; i += 256) {
        int qi = i / EQ, f = i - qi * EQ;
        int h = f / HD;
        float acc = 0.f;
#pragma unroll
        for (int ki = 0; ki < NB; ki++) acc = fmaf(P[h][qi][ki], Vs[ki][f], acc);
        o[(base + qi) * EQ + f] = __float2half(acc);
    }
}

// ---------------------------------------------------------------------------
// prop1 attention helpers
// ---------------------------------------------------------------------------
// row softmax: fp32 logits (2048 per row) -> fp16 probabilities
__global__ void __launch_bounds__(256)
softmax_kernel(const float* __restrict__ S, __half* __restrict__ P)
{
    const int q = blockIdx.x;
    const int h = blockIdx.y;
    const float* srow = S + ((size_t)h * SRC + q) * SRC;
    __half* prow = P + ((size_t)h * SRC + q) * SRC;
    __shared__ float red[256];
    const int tid = threadIdx.x;

    float v[8];
#pragma unroll
    for (int j = 0; j < 8; j++) v[j] = srow[tid + j * 256];

    float mx = -1e30f;
#pragma unroll
    for (int j = 0; j < 8; j++) mx = fmaxf(mx, v[j]);
    red[tid] = mx; __syncthreads();
    for (int w = 128; w > 0; w >>= 1) {
        if (tid < w) red[tid] = fmaxf(red[tid], red[tid + w]);
        __syncthreads();
    }
    mx = red[0]; __syncthreads();

    float sum = 0.f;
#pragma unroll
    for (int j = 0; j < 8; j++) { v[j] = expf(v[j] - mx); sum += v[j]; }
    red[tid] = sum; __syncthreads();
    for (int w = 128; w > 0; w >>= 1) {
        if (tid < w) red[tid] += red[tid + w];
        __syncthreads();
    }
    float inv = 1.f / red[0];
#pragma unroll
    for (int j = 0; j < 8; j++)
        prow[tid + j * 256] = __float2half(v[j] * inv);
}

// build Vt[h*HD + d][key] from kvp1h[key][544]; writes coalesced over key
__global__ void __launch_bounds__(256)
vt_kernel(const __half* __restrict__ kv, __half* __restrict__ vt)
{
    int i = blockIdx.x * 256 + threadIdx.x;   // over 2*HD*SRC
    if (i < 2 * HD * SRC) {
        int key = i & (SRC - 1);
        int r   = i >> 11;                    // h*HD + d
        vt[i] = kv[(size_t)key * 544 + EQ + r];
    }
}

// ---------------------------------------------------------------------------
// Host launch
// ---------------------------------------------------------------------------
extern "C" void kernel_launch(void* const* d_in, const int* in_sizes, int n_in,
                              void* d_out, int out_size)
{
    const float* emb0  = (const float*)d_in[0];
    const float* edge0 = (const float*)d_in[1];
    const float* td0   = (const float*)d_in[2];
    const float* emb1  = (const float*)d_in[3];
    const float* edge1 = (const float*)d_in[4];
    const float* td1   = (const float*)d_in[5];
    const float* emb2  = (const float*)d_in[6];
    const float* Wq    = (const float*)d_in[7];
    const float* bq    = (const float*)d_in[8];
    const float* Wk    = (const float*)d_in[9];
    const float* bk    = (const float*)d_in[10];
    const float* Wv    = (const float*)d_in[11];
    const float* bv    = (const float*)d_in[12];
    const float* Wo    = (const float*)d_in[13];
    const float* bo    = (const float*)d_in[14];
    const float* W1    = (const float*)d_in[15];
    const float* b1    = (const float*)d_in[16];
    const float* W2    = (const float*)d_in[17];
    const float* b2    = (const float*)d_in[18];
    float* out = (float*)d_out;

    float *kvp0, *qp0, *Sb, *zb;
    cudaGetSymbolAddress((void**)&kvp0, g_kvp0);
    cudaGetSymbolAddress((void**)&qp0,  g_qp0);
    cudaGetSymbolAddress((void**)&Sb,   g_S);
    cudaGetSymbolAddress((void**)&zb,   g_zb);

    __half *he0, *hg0, *ht0, *he1, *hg1, *ht1, *he2;
    __half *hWq, *hWk, *hWv, *hWo, *hW1, *hW2;
    __half *ho0, *ha0, *hh0, *ho1, *ha1, *hh1;
    __half *hkv1, *hq1, *hP, *hVt;
    cudaGetSymbolAddress((void**)&he0, hb_emb0);
    cudaGetSymbolAddress((void**)&hg0, hb_edge0);
    cudaGetSymbolAddress((void**)&ht0, hb_td0);
    cudaGetSymbolAddress((void**)&he1, hb_emb1);
    cudaGetSymbolAddress((void**)&hg1, hb_edge1);
    cudaGetSymbolAddress((void**)&ht1, hb_td1);
    cudaGetSymbolAddress((void**)&he2, hb_emb2);
    cudaGetSymbolAddress((void**)&hWq, hb_Wq);
    cudaGetSymbolAddress((void**)&hWk, hb_Wk);
    cudaGetSymbolAddress((void**)&hWv, hb_Wv);
    cudaGetSymbolAddress((void**)&hWo, hb_Wo);
    cudaGetSymbolAddress((void**)&hW1, hb_W1);
    cudaGetSymbolAddress((void**)&hW2, hb_W2);
    cudaGetSymbolAddress((void**)&ho0, hb_o0);
    cudaGetSymbolAddress((void**)&ha0, hb_a0);
    cudaGetSymbolAddress((void**)&hh0, hb_h0);
    cudaGetSymbolAddress((void**)&ho1, hb_o1);
    cudaGetSymbolAddress((void**)&ha1, hb_a1);
    cudaGetSymbolAddress((void**)&hh1, hb_h1);
    cudaGetSymbolAddress((void**)&hkv1, hb_kvp1);
    cudaGetSymbolAddress((void**)&hq1,  hb_qp1);
    cudaGetSymbolAddress((void**)&hP,   hb_P);
    cudaGetSymbolAddress((void**)&hVt,  hb_Vt);

    static cudaStream_t s2 = nullptr;
    static cudaEvent_t evFork = nullptr, evJoin = nullptr;
    if (s2 == nullptr) {
        cudaStreamCreateWithFlags(&s2, cudaStreamNonBlocking);
        cudaEventCreateWithFlags(&evFork, cudaEventDisableTiming);
        cudaEventCreateWithFlags(&evJoin, cudaEventDisableTiming);
    }
    cudaStream_t s0 = (cudaStream_t)0;

    const float scale = 1.0f / sqrtf((float)HD);
    cudaFuncSetAttribute(gemm_mma<1, 1, false, false>,
                         cudaFuncAttributeMaxDynamicSharedMemorySize, GM_SMEM);
    cudaFuncSetAttribute(gemm_mma<1, 1, false, true>,
                         cudaFuncAttributeMaxDynamicSharedMemorySize, GM_SMEM);
    cudaFuncSetAttribute(gemm_mma<2, 0, false, false>,
                         cudaFuncAttributeMaxDynamicSharedMemorySize, GM_SMEM);
    cudaFuncSetAttribute(gemm_mma<0, 0, false, true>,
                         cudaFuncAttributeMaxDynamicSharedMemorySize, GM_SMEM);
    cudaFuncSetAttribute(gemm_mma<3, 0, true, true>,
                         cudaFuncAttributeMaxDynamicSharedMemorySize, GM_SMEM);
    cudaFuncSetAttribute(gemm_mma<0, 0, false, false>,
                         cudaFuncAttributeMaxDynamicSharedMemorySize, GM_SMEM);

    // ---------------- fused fp16 conversion (single launch) -------------
    CvtArgs ca;
    ca.in[0]  = emb0;  ca.out[0]  = he0;
    ca.in[1]  = edge0; ca.out[1]  = hg0;
    ca.in[2]  = td0;   ca.out[2]  = ht0;
    ca.in[3]  = emb1;  ca.out[3]  = he1;
    ca.in[4]  = edge1; ca.out[4]  = hg1;
    ca.in[5]  = td1;   ca.out[5]  = ht1;
    ca.in[6]  = emb2;  ca.out[6]  = he2;
    ca.in[7]  = Wq;    ca.out[7]  = hWq;
    ca.in[8]  = Wk;    ca.out[8]  = hWk;
    ca.in[9]  = Wv;    ca.out[9]  = hWv;
    ca.in[10] = Wo;    ca.out[10] = hWo;
    ca.in[11] = W1;    ca.out[11] = hW1;
    ca.in[12] = W2;    ca.out[12] = hW2;
    cvt_all<<<4736, 256, 0, s0>>>(ca);

    // ---------------- fork ----------------
    cudaEventRecord(evFork, s0);
    cudaStreamWaitEvent(s2, evFork, 0);

    // ---------------- propagation 1 + passthrough (side stream) ---------
    cudaMemcpyAsync(out + OUT_EDGE, edge1,
                    (size_t)SRC * NB * EDIM * sizeof(float),
                    cudaMemcpyDeviceToDevice, s2);
    cudaMemcpyAsync(out + OUT_TD, td1,
                    (size_t)SRC * NB * TDIM * sizeof(float),
                    cudaMemcpyDeviceToDevice, s2);
    // K/V projection -> fp16
    gemm_mma<1, 1, false, true><<<dim3(9, 16), 256, GM_SMEM, s2>>>(
        he1, hg1, ht1, 0, hWk, hWv, KDT, bk, bv,
        hkv1, M1, 544, KDT, 544, 1.f);
    // Q projection (q = [emb2, 0]) -> fp16, scale folded in
    gemm_mma<0, 0, false, true><<<dim3(5, 16), 256, GM_SMEM, s2>>>(
        he2, nullptr, nullptr, DDIM, hWq, nullptr, EQ, bq, nullptr,
        hq1, M1, EQ, DDIM, EQ, scale);
    // V transpose for PV GEMM
    vt_kernel<<<(2 * HD * SRC + 255) / 256, 256, 0, s2>>>(hkv1, hVt);
    // S_h = Q_h K_h^T  (fp32 logits)
    for (int h = 0; h < 2; h++) {
        gemm_mma<0, 0, false, false><<<dim3(32, 16), 256, GM_SMEM, s2>>>(
            hq1 + h * HD, nullptr, nullptr, EQ,
            hkv1 + h * HD, nullptr, 544, zb, nullptr,
            Sb + (size_t)h * SRC * SRC, SRC, SRC, HD, SRC, 1.f);
    }
    // row softmax -> fp16 P
    softmax_kernel<<<dim3(SRC, 2), 256, 0, s2>>>(Sb, hP);
    // O_h = P_h V_h  (fp16 out, straight into ho1 head slice)
    for (int h = 0; h < 2; h++) {
        gemm_mma<0, 0, false, true><<<dim3(3, 16), 256, GM_SMEM, s2>>>(
            hP + (size_t)h * SRC * SRC, nullptr, nullptr, SRC,
            hVt + (size_t)h * HD * SRC, nullptr, SRC, zb, nullptr,
            ho1 + h * HD, SRC, HD, SRC, EQ, 1.f);
    }
    gemm_mma<0, 0, false, true><<<dim3(5, 16), 256, GM_SMEM, s2>>>(
        ho1, nullptr, nullptr, EQ, hWo, nullptr, EQ, bo, nullptr,
        ha1, M1, EQ, EQ, EQ, 1.f);
    gemm_mma<3, 0, true, true><<<dim3(3, 16), 256, GM_SMEM, s2>>>(
        ha1, he2, nullptr, 0, hW1, nullptr, EQ + DDIM, b1, nullptr,
        hh1, M1, DDIM, EQ + DDIM, DDIM, 1.f);
    gemm_mma<0, 0, false, false><<<dim3(3, 16), 256, GM_SMEM, s2>>>(
        hh1, nullptr, nullptr, DDIM, hW2, nullptr, DDIM, b2, nullptr,
        out + OUT_R1, M1, DDIM, DDIM, DDIM, 1.f);
    cudaEventRecord(evJoin, s2);

    // ---------------- propagation 0 (main stream) ----------------
    gemm_mma<1, 1, false, false><<<dim3(9, 160), 256, GM_SMEM, s0>>>(
        he0, hg0, ht0, 0, hWk, hWv, KDT, bk, bv,
        kvp0, M0, 544, KDT, 544, 1.f);
    gemm_mma<2, 0, false, false><<<dim3(5, 160), 256, GM_SMEM, s0>>>(
        he1, ht1, nullptr, 0, hWq, nullptr, EQ, bq, nullptr,
        qp0, M0, EQ, EQ, EQ, scale);
    attn0_kernel<<<SRC, 256, 0, s0>>>(qp0, kvp0, ho0);
    gemm_mma<0, 0, false, true><<<dim3(5, 160), 256, GM_SMEM, s0>>>(
        ho0, nullptr, nullptr, EQ, hWo, nullptr, EQ, bo, nullptr,
        ha0, M0, EQ, EQ, EQ, 1.f);
    gemm_mma<3, 0, true, true><<<dim3(3, 160), 256, GM_SMEM, s0>>>(
        ha0, he1, nullptr, 0, hW1, nullptr, EQ + DDIM, b1, nullptr,
        hh0, M0, DDIM, EQ + DDIM, DDIM, 1.f);
    gemm_mma<0, 0, false, false><<<dim3(3, 160), 256, GM_SMEM, s0>>>(
        hh0, nullptr, nullptr, DDIM, hW2, nullptr, DDIM, b2, nullptr,
        out + OUT_R0, M0, DDIM, DDIM, DDIM, 1.f);

    // ---------------- join ----------------
    cudaStreamWaitEvent(s0, evJoin, 0);
}

// round 15
// speedup vs baseline: 1.7661x; 1.1138x over previous
#include <cuda_runtime.h>
#include <cuda_fp16.h>
#include <math.h>
#include <stdint.h>

// ---------------------------------------------------------------------------
// Problem constants
// ---------------------------------------------------------------------------
#define SRC   2048          // S
#define NB    10            // neighbors
#define DDIM  172           // D
#define EDIM  172           // EDGE
#define TDIM  100           // TD
#define EQ    272           // E  = D + TD
#define KD    444           // D + EDGE + TD
#define KDT   4440          // KD * N
#define HD    136           // head dim (E / H)

#define M0    (SRC*NB)      // 20480 rows prop0
#define M1    SRC           // 2048  rows prop1

#define PD176 176           // padded 172-stride
#define PD448 448           // padded 444-stride

// output layout offsets (float elements)
#define OUT_R0    0
#define OUT_R1    (SRC*NB*DDIM)
#define OUT_EDGE  (OUT_R1 + SRC*DDIM)
#define OUT_TD    (OUT_EDGE + SRC*NB*EDIM)

// ---------------------------------------------------------------------------
// Scratch (device globals; no allocation allowed)
// ---------------------------------------------------------------------------
__device__ float g_kvp0[M0 * 544];
__device__ float g_qp0 [M0 * EQ];
__device__ float g_S [2 * SRC * SRC];        // prop1 logits, fp32
__device__ float g_zb[SRC];                  // zero bias (static zero-init)

// fp16 packed GEMM operands
__device__ __half hb_n0  [M0 * KDT];         // packed neigh0
__device__ __half hb_n1  [M1 * KDT];         // packed neigh1
__device__ __half hb_qin0[M0 * EQ];          // packed (emb1|td1)
__device__ __half hb_emb1p[M0 * PD176];      // emb1 padded
__device__ __half hb_emb2p[SRC * PD176];     // emb2 padded
__device__ __half hb_Wq[EQ*EQ];
__device__ __half hb_Wk[EQ*KDT];
__device__ __half hb_Wv[EQ*KDT];
__device__ __half hb_Wo[EQ*EQ];
__device__ __half hb_W1p[DDIM * PD448];
__device__ __half hb_W2p[DDIM * PD176];
// fp16 intermediates
__device__ __half hb_o0[M0*EQ];
__device__ __half hb_a0[M0*EQ];
__device__ __half hb_h0[M0*PD176];
__device__ __half hb_kvp1[M1*544];
__device__ __half hb_qp1 [M1*EQ];
__device__ __half hb_P  [2 * SRC * SRC];
__device__ __half hb_Vt [2 * HD * SRC];
__device__ __half hb_o1[M1*EQ];
__device__ __half hb_a1[M1*EQ];
__device__ __half hb_h1[M1*PD176];

// ---------------------------------------------------------------------------
// Fused fp32 -> fp16 convert + pack (one launch).
// Segments (float4 units of SOURCE data):
//  0 n0 pack   1 n1 pack   2 qin0 pack   3 emb1p   4 emb2p
//  5 Wq   6 Wk   7 Wv   8 Wo   9 W1p   10 W2p
// ---------------------------------------------------------------------------
struct CvtArgs {
    const float *emb0, *edge0, *td0, *emb1, *edge1, *td1, *emb2;
    const float *Wq, *Wk, *Wv, *Wo, *W1, *W2;
};

#define O0  0
#define O1  22732800
#define O2  25006080
#define O3  26398720
#define O4  27279360
#define O5  27367424
#define O6  27385920
#define O7  27687840
#define O8  27989760
#define O9  28008256
#define O10 28027348
#define O11 28034744

__device__ __forceinline__ uint2 pack4(const float* src) {
    float4 v = *reinterpret_cast<const float4*>(src);
    __half2 h0 = __float22half2_rn(make_float2(v.x, v.y));
    __half2 h1 = __float22half2_rn(make_float2(v.z, v.w));
    uint2 u;
    u.x = *reinterpret_cast<const uint32_t*>(&h0);
    u.y = *reinterpret_cast<const uint32_t*>(&h1);
    return u;
}

__global__ void __launch_bounds__(256)
cvt_all(CvtArgs a)
{
    const int stride = gridDim.x * blockDim.x;
    for (int i = blockIdx.x * blockDim.x + threadIdx.x; i < O11; i += stride) {
        if (i < O1) {                       // n0 pack
            int li = i;
            int row = li / 1110, f4 = li - row * 1110;
            int k = f4 * 4, n2 = f4 / 111, f = k - n2 * KD;
            size_t sub = (size_t)row * NB + n2;
            const float* s = (f < DDIM)   ? a.emb0  + sub * DDIM + f
                           : (f < 2*DDIM) ? a.edge0 + sub * EDIM + (f - DDIM)
                                          : a.td0   + sub * TDIM + (f - 2*DDIM);
            reinterpret_cast<uint2*>(hb_n0)[li] = pack4(s);
        } else if (i < O2) {                // n1 pack
            int li = i - O1;
            int row = li / 1110, f4 = li - row * 1110;
            int k = f4 * 4, n2 = f4 / 111, f = k - n2 * KD;
            size_t sub = (size_t)row * NB + n2;
            const float* s = (f < DDIM)   ? a.emb1  + sub * DDIM + f
                           : (f < 2*DDIM) ? a.edge1 + sub * EDIM + (f - DDIM)
                                          : a.td1   + sub * TDIM + (f - 2*DDIM);
            reinterpret_cast<uint2*>(hb_n1)[li] = pack4(s);
        } else if (i < O3) {                // qin0 pack
            int li = i - O2;
            int row = li / 68, c4 = li - row * 68;
            int k = c4 * 4;
            const float* s = (k < DDIM) ? a.emb1 + (size_t)row * DDIM + k
                                        : a.td1  + (size_t)row * TDIM + (k - DDIM);
            reinterpret_cast<uint2*>(hb_qin0)[li] = pack4(s);
        } else if (i < O4) {                // emb1p
            int li = i - O3;
            int row = li / 43, c4 = li - row * 43;
            reinterpret_cast<uint2*>(hb_emb1p)[row * 44 + c4] =
                pack4(a.emb1 + (size_t)row * DDIM + c4 * 4);
        } else if (i < O5) {                // emb2p
            int li = i - O4;
            int row = li / 43, c4 = li - row * 43;
            reinterpret_cast<uint2*>(hb_emb2p)[row * 44 + c4] =
                pack4(a.emb2 + (size_t)row * DDIM + c4 * 4);
        } else if (i < O6) {                // Wq dense
            int li = i - O5;
            reinterpret_cast<uint2*>(hb_Wq)[li] = pack4(a.Wq + (size_t)li * 4);
        } else if (i < O7) {                // Wk dense
            int li = i - O6;
            reinterpret_cast<uint2*>(hb_Wk)[li] = pack4(a.Wk + (size_t)li * 4);
        } else if (i < O8) {                // Wv dense
            int li = i - O7;
            reinterpret_cast<uint2*>(hb_Wv)[li] = pack4(a.Wv + (size_t)li * 4);
        } else if (i < O9) {                // Wo dense
            int li = i - O8;
            reinterpret_cast<uint2*>(hb_Wo)[li] = pack4(a.Wo + (size_t)li * 4);
        } else if (i < O10) {               // W1p
            int li = i - O9;
            int row = li / 111, c4 = li - row * 111;
            reinterpret_cast<uint2*>(hb_W1p)[row * 112 + c4] =
                pack4(a.W1 + (size_t)row * KD + c4 * 4);
        } else {                            // W2p
            int li = i - O10;
            int row = li / 43, c4 = li - row * 43;
            reinterpret_cast<uint2*>(hb_W2p)[row * 44 + c4] =
                pack4(a.W2 + (size_t)row * DDIM + c4 * 4);
        }
    }
}

// ---------------------------------------------------------------------------
// A/B address functors.
//   AMODE 0: dense A0[row*lda + k]
//   AMODE 3: concat a(272, lda=272) | b(172, padded ld=176)
//   BMODE 0: dense; BMODE 1: Wk|Wv split at n=272, ldb=KDT
// ---------------------------------------------------------------------------
template<int MODE>
__device__ __forceinline__ const __half* addrA(const __half* __restrict__ A0,
                                               const __half* __restrict__ A1,
                                               int lda, int row, int k)
{
    if (MODE == 0) return A0 + (size_t)row * lda + k;
    if (k < EQ)    return A0 + (size_t)row * EQ + k;
    return A1 + (size_t)row * PD176 + (k - EQ);
}

template<int MODE>
__device__ __forceinline__ const __half* addrB(const __half* __restrict__ B0,
                                               const __half* __restrict__ B1,
                                               int ldb, int n, int k)
{
    if (MODE == 0) return B0 + (size_t)n * ldb + k;
    if (n < EQ)    return B0 + (size_t)n * KDT + k;
    return B1 + (size_t)(n - EQ) * KDT + k;
}

// ---------------------------------------------------------------------------
// PTX helpers
// ---------------------------------------------------------------------------
__device__ __forceinline__ uint32_t smem_u32(const void* p) {
    uint32_t a;
    asm("{ .reg .u64 t; cvta.to.shared.u64 t, %1; cvt.u32.u64 %0, t; }"
        : "=r"(a) : "l"(p));
    return a;
}

// 16B cp.async.cg with zero-fill for src_bytes < 16
__device__ __forceinline__ void cp_async16(uint32_t smem, const void* gmem,
                                           int src_bytes) {
    asm volatile("cp.async.cg.shared.global [%0], [%1], 16, %2;"
                 :: "r"(smem), "l"(gmem), "r"(src_bytes));
}
#define CP_COMMIT() asm volatile("cp.async.commit_group;")
#define CP_WAIT2()  asm volatile("cp.async.wait_group 2;")

__device__ __forceinline__ void ldsm_x4(uint32_t r[4], uint32_t addr) {
    asm volatile("ldmatrix.sync.aligned.m8n8.x4.shared.b16 {%0,%1,%2,%3}, [%4];"
        : "=r"(r[0]), "=r"(r[1]), "=r"(r[2]), "=r"(r[3]) : "r"(addr));
}

__device__ __forceinline__ void mma_f16(float c[4], const uint32_t a[4],
                                        uint32_t b0, uint32_t b1) {
    asm volatile(
        "mma.sync.aligned.m16n8k16.row.col.f32.f16.f16.f32 "
        "{%0,%1,%2,%3}, {%4,%5,%6,%7}, {%8,%9}, {%0,%1,%2,%3};"
        : "+f"(c[0]), "+f"(c[1]), "+f"(c[2]), "+f"(c[3])
        : "r"(a[0]), "r"(a[1]), "r"(a[2]), "r"(a[3]), "r"(b0), "r"(b1));
}

// ---------------------------------------------------------------------------
// mma.sync fp16 GEMM, 4-stage cp.async.cg(16B) pipeline + ldmatrix.
// CTA tile 128x64xBK32, 256 threads (8 warps, 4x2), warp tile 32x32.
// Requires: row strides of all operands 16B-aligned (padded); concat
// boundary at 272 (%8==0); K-tails via cp.async zfill.
// ---------------------------------------------------------------------------
#define STAGES  4
#define ROWB    80
#define A_STG   10240
#define B_STG   5120
#define B_OFF   (STAGES * A_STG)
#define GM_SMEM (B_OFF + STAGES * B_STG)   // 61440

template<int AMODE, int BMODE, bool RELU, bool OUT16>
__global__ void __launch_bounds__(256)
gemm_mma(const __half* __restrict__ A0, const __half* __restrict__ A1,
         int lda,
         const __half* __restrict__ B0, const __half* __restrict__ B1, int ldb,
         const float* __restrict__ bias0, const float* __restrict__ bias1,
         void* __restrict__ Cv, int M, int N, int K, int ldc, float alpha)
{
    extern __shared__ char sh[];
    const uint32_t sbase = smem_u32(sh);

    const int tid  = threadIdx.x;
    const int wid  = tid >> 5;
    const int lane = tid & 31;
    const int g    = lane >> 2;
    const int t    = lane & 3;
    const int wm   = wid & 3;
    const int wn   = wid >> 2;
    const int m0   = blockIdx.y * 128;
    const int n0   = blockIdx.x * 64;

    const uint32_t a_lm = (uint32_t)(wm * 32 + (lane & 7) + ((lane >> 3) & 1) * 8) * ROWB
                        + ((lane >> 4) & 1) * 16;
    const uint32_t b_lm = (uint32_t)(wn * 32 + (lane & 7) + ((lane >> 4) & 1) * 8) * ROWB
                        + ((lane >> 3) & 1) * 16;

    float acc[2][4][4];
#pragma unroll
    for (int i = 0; i < 2; i++)
#pragma unroll
        for (int j = 0; j < 4; j++)
#pragma unroll
            for (int l = 0; l < 4; l++) acc[i][j][l] = 0.f;

    // staging: 16B chunks; thread -> (row 0..63, chunk 0..3)
    const int sr = tid >> 2;
    const int sc = tid & 3;
    const int KT = (K + 31) / 32;

#define ISSUE(st_, k0_)                                                        \
    do {                                                                       \
        const uint32_t abase = sbase + (st_) * A_STG;                          \
        const uint32_t bbase = sbase + B_OFF + (st_) * B_STG;                  \
        const int gk = (k0_) + sc * 8;                                         \
        int bk = (K - gk) * 2;                                                 \
        bk = bk < 0 ? 0 : (bk > 16 ? 16 : bk);                                 \
        const int gks = bk ? gk : 0;                                           \
        _Pragma("unroll")                                                      \
        for (int p = 0; p < 2; p++) {                                          \
            int r = sr + p * 64;                                               \
            const __half* src = addrA<AMODE>(A0, A1, lda, m0 + r, gks);        \
            cp_async16(abase + r * ROWB + sc * 16, src, bk);                   \
        }                                                                      \
        {                                                                      \
            int gn = n0 + sr;                                                  \
            int bb = (gn < N) ? bk : 0;                                        \
            const __half* src = addrB<BMODE>(B0, B1, ldb, bb ? gn : 0, gks);   \
            cp_async16(bbase + sr * ROWB + sc * 16, src, bb);                  \
        }                                                                      \
    } while (0)

    ISSUE(0, 0);  CP_COMMIT();
    ISSUE(1, 32); CP_COMMIT();
    ISSUE(2, 64); CP_COMMIT();
    CP_WAIT2();
    __syncthreads();

    int st = 0;
    for (int it = 0; it < KT; ++it) {
        int st3 = st + 3; if (st3 >= STAGES) st3 -= STAGES;
        if (it + 3 < KT) ISSUE(st3, (it + 3) * 32);
        CP_COMMIT();

        const uint32_t Abu = sbase + st * A_STG + a_lm;
        const uint32_t Bbu = sbase + B_OFF + st * B_STG + b_lm;
#pragma unroll
        for (int ks = 0; ks < 2; ks++) {
            uint32_t af[2][4], bq[2][4];
#pragma unroll
            for (int mt = 0; mt < 2; mt++)
                ldsm_x4(af[mt], Abu + mt * (16 * ROWB) + ks * 32);
#pragma unroll
            for (int ntp = 0; ntp < 2; ntp++)
                ldsm_x4(bq[ntp], Bbu + ntp * (16 * ROWB) + ks * 32);
#pragma unroll
            for (int mt = 0; mt < 2; mt++)
#pragma unroll
                for (int ntp = 0; ntp < 2; ntp++) {
                    mma_f16(acc[mt][2*ntp + 0], af[mt], bq[ntp][0], bq[ntp][1]);
                    mma_f16(acc[mt][2*ntp + 1], af[mt], bq[ntp][2], bq[ntp][3]);
                }
        }

        CP_WAIT2();
        __syncthreads();
        if (++st >= STAGES) st = 0;
    }

#pragma unroll
    for (int mt = 0; mt < 2; mt++) {
        int row0 = m0 + wm * 32 + mt * 16 + g;
#pragma unroll
        for (int nt = 0; nt < 4; nt++) {
            int col = n0 + wn * 32 + nt * 8 + t * 2;
#pragma unroll
            for (int half_ = 0; half_ < 2; half_++) {
                int gm = row0 + half_ * 8;
                if (gm >= M) continue;
#pragma unroll
                for (int cc = 0; cc < 2; cc++) {
                    int gn = col + cc;
                    if (gn >= N) continue;
                    float bval = (BMODE == 1)
                               ? (gn < EQ ? bias0[gn] : bias1[gn - EQ])
                               : bias0[gn];
                    float v = (acc[mt][nt][half_ * 2 + cc] + bval) * alpha;
                    if (RELU) v = fmaxf(v, 0.f);
                    if (OUT16)
                        ((__half*)Cv)[(size_t)gm * ldc + gn] = __float2half(v);
                    else
                        ((float*)Cv)[(size_t)gm * ldc + gn] = v;
                }
            }
        }
    }
#undef ISSUE
}

// ---------------------------------------------------------------------------
// Attention prop0: per node, 2 heads, 10x10, hd=136.  Emits fp16 o.
// ---------------------------------------------------------------------------
__global__ void __launch_bounds__(256)
attn0_kernel(const float* __restrict__ qp, const float* __restrict__ kvp,
             __half* __restrict__ o)
{
    __shared__ float Qs[NB][EQ];
    __shared__ float Ks[NB][EQ];
    __shared__ float Vs[NB][EQ];
    __shared__ float P[2][NB][NB];

    const int s = blockIdx.x;
    const int tid = threadIdx.x;
    const size_t base = (size_t)s * NB;

    for (int i = tid; i < NB * EQ; i += 256) {
        int r = i / EQ, f = i - r * EQ;
        Qs[r][f] = qp[(base + r) * EQ + f];
        Ks[r][f] = kvp[(base + r) * 544 + f];
        Vs[r][f] = kvp[(base + r) * 544 + EQ + f];
    }
    __syncthreads();

    if (tid < 200) {
        int h = tid / 100, rem = tid - h * 100;
        int qi = rem / NB, ki = rem - qi * NB;
        const float* q = &Qs[qi][h * HD];
        const float* k = &Ks[ki][h * HD];
        float acc = 0.f;
#pragma unroll 8
        for (int d = 0; d < HD; d++) acc = fmaf(q[d], k[d], acc);
        P[h][qi][ki] = acc;
    }
    __syncthreads();

    if (tid < 20) {
        int h = tid / NB, qi = tid - h * NB;
        float mx = -1e30f;
#pragma unroll
        for (int ki = 0; ki < NB; ki++) mx = fmaxf(mx, P[h][qi][ki]);
        float sum = 0.f;
#pragma unroll
        for (int ki = 0; ki < NB; ki++) {
            float e = expf(P[h][qi][ki] - mx);
            P[h][qi][ki] = e;
            sum += e;
        }
        float inv = 1.f / sum;
#pragma unroll
        for (int ki = 0; ki < NB; ki++) P[h][qi][ki] *= inv;
    }
    __syncthreads();

    for (int i = tid; i < NB * EQ; i += 256) {
        int qi = i / EQ, f = i - qi * EQ;
        int h = f / HD;
        float acc = 0.f;
#pragma unroll
        for (int ki = 0; ki < NB; ki++) acc = fmaf(P[h][qi][ki], Vs[ki][f], acc);
        o[(base + qi) * EQ + f] = __float2half(acc);
    }
}

// ---------------------------------------------------------------------------
// prop1 attention helpers
// ---------------------------------------------------------------------------
__global__ void __launch_bounds__(256)
softmax_kernel(const float* __restrict__ S, __half* __restrict__ P)
{
    const int q = blockIdx.x;
    const int h = blockIdx.y;
    const float* srow = S + ((size_t)h * SRC + q) * SRC;
    __half* prow = P + ((size_t)h * SRC + q) * SRC;
    __shared__ float red[256];
    const int tid = threadIdx.x;

    float v[8];
#pragma unroll
    for (int j = 0; j < 8; j++) v[j] = srow[tid + j * 256];

    float mx = -1e30f;
#pragma unroll
    for (int j = 0; j < 8; j++) mx = fmaxf(mx, v[j]);
    red[tid] = mx; __syncthreads();
    for (int w = 128; w > 0; w >>= 1) {
        if (tid < w) red[tid] = fmaxf(red[tid], red[tid + w]);
        __syncthreads();
    }
    mx = red[0]; __syncthreads();

    float sum = 0.f;
#pragma unroll
    for (int j = 0; j < 8; j++) { v[j] = expf(v[j] - mx); sum += v[j]; }
    red[tid] = sum; __syncthreads();
    for (int w = 128; w > 0; w >>= 1) {
        if (tid < w) red[tid] += red[tid + w];
        __syncthreads();
    }
    float inv = 1.f / red[0];
#pragma unroll
    for (int j = 0; j < 8; j++)
        prow[tid + j * 256] = __float2half(v[j] * inv);
}

__global__ void __launch_bounds__(256)
vt_kernel(const __half* __restrict__ kv, __half* __restrict__ vt)
{
    int i = blockIdx.x * 256 + threadIdx.x;
    if (i < 2 * HD * SRC) {
        int key = i & (SRC - 1);
        int r   = i >> 11;
        vt[i] = kv[(size_t)key * 544 + EQ + r];
    }
}

// ---------------------------------------------------------------------------
// Host launch
// ---------------------------------------------------------------------------
extern "C" void kernel_launch(void* const* d_in, const int* in_sizes, int n_in,
                              void* d_out, int out_size)
{
    const float* emb0  = (const float*)d_in[0];
    const float* edge0 = (const float*)d_in[1];
    const float* td0   = (const float*)d_in[2];
    const float* emb1  = (const float*)d_in[3];
    const float* edge1 = (const float*)d_in[4];
    const float* td1   = (const float*)d_in[5];
    const float* emb2  = (const float*)d_in[6];
    const float* Wq    = (const float*)d_in[7];
    const float* bq    = (const float*)d_in[8];
    const float* Wk    = (const float*)d_in[9];
    const float* bk    = (const float*)d_in[10];
    const float* Wv    = (const float*)d_in[11];
    const float* bv    = (const float*)d_in[12];
    const float* Wo    = (const float*)d_in[13];
    const float* bo    = (const float*)d_in[14];
    const float* W1    = (const float*)d_in[15];
    const float* b1    = (const float*)d_in[16];
    const float* W2    = (const float*)d_in[17];
    const float* b2    = (const float*)d_in[18];
    float* out = (float*)d_out;

    float *kvp0, *qp0, *Sb, *zb;
    cudaGetSymbolAddress((void**)&kvp0, g_kvp0);
    cudaGetSymbolAddress((void**)&qp0,  g_qp0);
    cudaGetSymbolAddress((void**)&Sb,   g_S);
    cudaGetSymbolAddress((void**)&zb,   g_zb);

    __half *hn0, *hn1, *hqin0, *he1p, *he2p;
    __half *hWq, *hWk, *hWv, *hWo, *hW1p, *hW2p;
    __half *ho0, *ha0, *hh0, *ho1, *ha1, *hh1;
    __half *hkv1, *hq1, *hP, *hVt;
    cudaGetSymbolAddress((void**)&hn0,  hb_n0);
    cudaGetSymbolAddress((void**)&hn1,  hb_n1);
    cudaGetSymbolAddress((void**)&hqin0, hb_qin0);
    cudaGetSymbolAddress((void**)&he1p, hb_emb1p);
    cudaGetSymbolAddress((void**)&he2p, hb_emb2p);
    cudaGetSymbolAddress((void**)&hWq, hb_Wq);
    cudaGetSymbolAddress((void**)&hWk, hb_Wk);
    cudaGetSymbolAddress((void**)&hWv, hb_Wv);
    cudaGetSymbolAddress((void**)&hWo, hb_Wo);
    cudaGetSymbolAddress((void**)&hW1p, hb_W1p);
    cudaGetSymbolAddress((void**)&hW2p, hb_W2p);
    cudaGetSymbolAddress((void**)&ho0, hb_o0);
    cudaGetSymbolAddress((void**)&ha0, hb_a0);
    cudaGetSymbolAddress((void**)&hh0, hb_h0);
    cudaGetSymbolAddress((void**)&ho1, hb_o1);
    cudaGetSymbolAddress((void**)&ha1, hb_a1);
    cudaGetSymbolAddress((void**)&hh1, hb_h1);
    cudaGetSymbolAddress((void**)&hkv1, hb_kvp1);
    cudaGetSymbolAddress((void**)&hq1,  hb_qp1);
    cudaGetSymbolAddress((void**)&hP,   hb_P);
    cudaGetSymbolAddress((void**)&hVt,  hb_Vt);

    static cudaStream_t s2 = nullptr;
    static cudaEvent_t evFork = nullptr, evJoin = nullptr;
    if (s2 == nullptr) {
        cudaStreamCreateWithFlags(&s2, cudaStreamNonBlocking);
        cudaEventCreateWithFlags(&evFork, cudaEventDisableTiming);
        cudaEventCreateWithFlags(&evJoin, cudaEventDisableTiming);
    }
    cudaStream_t s0 = (cudaStream_t)0;

    const float scale = 1.0f / sqrtf((float)HD);
    cudaFuncSetAttribute(gemm_mma<0, 1, false, false>,
                         cudaFuncAttributeMaxDynamicSharedMemorySize, GM_SMEM);
    cudaFuncSetAttribute(gemm_mma<0, 1, false, true>,
                         cudaFuncAttributeMaxDynamicSharedMemorySize, GM_SMEM);
    cudaFuncSetAttribute(gemm_mma<0, 0, false, true>,
                         cudaFuncAttributeMaxDynamicSharedMemorySize, GM_SMEM);
    cudaFuncSetAttribute(gemm_mma<3, 0, true, true>,
                         cudaFuncAttributeMaxDynamicSharedMemorySize, GM_SMEM);
    cudaFuncSetAttribute(gemm_mma<0, 0, false, false>,
                         cudaFuncAttributeMaxDynamicSharedMemorySize, GM_SMEM);

    // ---------------- fused convert + pack (single launch) -------------
    CvtArgs ca;
    ca.emb0 = emb0; ca.edge0 = edge0; ca.td0 = td0;
    ca.emb1 = emb1; ca.edge1 = edge1; ca.td1 = td1;
    ca.emb2 = emb2;
    ca.Wq = Wq; ca.Wk = Wk; ca.Wv = Wv; ca.Wo = Wo; ca.W1 = W1; ca.W2 = W2;
    cvt_all<<<4736, 256, 0, s0>>>(ca);

    // ---------------- fork ----------------
    cudaEventRecord(evFork, s0);
    cudaStreamWaitEvent(s2, evFork, 0);

    // ---------------- propagation 1 + passthrough (side stream) ---------
    cudaMemcpyAsync(out + OUT_EDGE, edge1,
                    (size_t)SRC * NB * EDIM * sizeof(float),
                    cudaMemcpyDeviceToDevice, s2);
    cudaMemcpyAsync(out + OUT_TD, td1,
                    (size_t)SRC * NB * TDIM * sizeof(float),
                    cudaMemcpyDeviceToDevice, s2);
    gemm_mma<0, 1, false, true><<<dim3(9, 16), 256, GM_SMEM, s2>>>(
        hn1, nullptr, KDT, hWk, hWv, KDT, bk, bv,
        hkv1, M1, 544, KDT, 544, 1.f);
    gemm_mma<0, 0, false, true><<<dim3(5, 16), 256, GM_SMEM, s2>>>(
        he2p, nullptr, PD176, hWq, nullptr, EQ, bq, nullptr,
        hq1, M1, EQ, DDIM, EQ, scale);
    vt_kernel<<<(2 * HD * SRC + 255) / 256, 256, 0, s2>>>(hkv1, hVt);
    for (int h = 0; h < 2; h++) {
        gemm_mma<0, 0, false, false><<<dim3(32, 16), 256, GM_SMEM, s2>>>(
            hq1 + h * HD, nullptr, EQ,
            hkv1 + h * HD, nullptr, 544, zb, nullptr,
            Sb + (size_t)h * SRC * SRC, SRC, SRC, HD, SRC, 1.f);
    }
    softmax_kernel<<<dim3(SRC, 2), 256, 0, s2>>>(Sb, hP);
    for (int h = 0; h < 2; h++) {
        gemm_mma<0, 0, false, true><<<dim3(3, 16), 256, GM_SMEM, s2>>>(
            hP + (size_t)h * SRC * SRC, nullptr, SRC,
            hVt + (size_t)h * HD * SRC, nullptr, SRC, zb, nullptr,
            ho1 + h * HD, SRC, HD, SRC, EQ, 1.f);
    }
    gemm_mma<0, 0, false, true><<<dim3(5, 16), 256, GM_SMEM, s2>>>(
        ho1, nullptr, EQ, hWo, nullptr, EQ, bo, nullptr,
        ha1, M1, EQ, EQ, EQ, 1.f);
    gemm_mma<3, 0, true, true><<<dim3(3, 16), 256, GM_SMEM, s2>>>(
        ha1, he2p, 0, hW1p, nullptr, PD448, b1, nullptr,
        hh1, M1, DDIM, KD, PD176, 1.f);
    gemm_mma<0, 0, false, false><<<dim3(3, 16), 256, GM_SMEM, s2>>>(
        hh1, nullptr, PD176, hW2p, nullptr, PD176, b2, nullptr,
        out + OUT_R1, M1, DDIM, DDIM, DDIM, 1.f);
    cudaEventRecord(evJoin, s2);

    // ---------------- propagation 0 (main stream) ----------------
    gemm_mma<0, 1, false, false><<<dim3(9, 160), 256, GM_SMEM, s0>>>(
        hn0, nullptr, KDT, hWk, hWv, KDT, bk, bv,
        kvp0, M0, 544, KDT, 544, 1.f);
    gemm_mma<0, 0, false, false><<<dim3(5, 160), 256, GM_SMEM, s0>>>(
        hqin0, nullptr, EQ, hWq, nullptr, EQ, bq, nullptr,
        qp0, M0, EQ, EQ, EQ, scale);
    attn0_kernel<<<SRC, 256, 0, s0>>>(qp0, kvp0, ho0);
    gemm_mma<0, 0, false, true><<<dim3(5, 160), 256, GM_SMEM, s0>>>(
        ho0, nullptr, EQ, hWo, nullptr, EQ, bo, nullptr,
        ha0, M0, EQ, EQ, EQ, 1.f);
    gemm_mma<3, 0, true, true><<<dim3(3, 160), 256, GM_SMEM, s0>>>(
        ha0, he1p, 0, hW1p, nullptr, PD448, b1, nullptr,
        hh0, M0, DDIM, KD, PD176, 1.f);
    gemm_mma<0, 0, false, false><<<dim3(3, 160), 256, GM_SMEM, s0>>>(
        hh0, nullptr, PD176, hW2p, nullptr, PD176, b2, nullptr,
        out + OUT_R0, M0, DDIM, DDIM, DDIM, 1.f);

    // ---------------- join ----------------
    cudaStreamWaitEvent(s0, evJoin, 0);
}

// round 16
// speedup vs baseline: 1.7671x; 1.0006x over previous
#include <cuda_runtime.h>
#include <cuda_fp16.h>
#include <math.h>
#include <stdint.h>

// ---------------------------------------------------------------------------
// Problem constants
// ---------------------------------------------------------------------------
#define SRC   2048          // S
#define NB    10            // neighbors
#define DDIM  172           // D
#define EDIM  172           // EDGE
#define TDIM  100           // TD
#define EQ    272           // E  = D + TD
#define KD    444           // D + EDGE + TD
#define KDT   4440          // KD * N
#define HD    136           // head dim (E / H)

#define M0    (SRC*NB)      // 20480 rows prop0
#define M1    SRC           // 2048  rows prop1

#define PD176 176           // padded 172-stride
#define PD448 448           // padded 444-stride

// output layout offsets (float elements)
#define OUT_R0    0
#define OUT_R1    (SRC*NB*DDIM)
#define OUT_EDGE  (OUT_R1 + SRC*DDIM)
#define OUT_TD    (OUT_EDGE + SRC*NB*EDIM)

// ---------------------------------------------------------------------------
// Scratch (device globals; no allocation allowed)
// ---------------------------------------------------------------------------
__device__ float g_kvp0[M0 * 544];
__device__ float g_qp0 [M0 * EQ];
__device__ float g_S [2 * SRC * SRC];        // prop1 logits, fp32
__device__ float g_zb[SRC];                  // zero bias (static zero-init)

// fp16 packed GEMM operands
__device__ __half hb_n0  [M0 * KDT];         // packed neigh0
__device__ __half hb_n1  [M1 * KDT];         // packed neigh1
__device__ __half hb_qin0[M0 * EQ];          // packed (emb1|td1)
__device__ __half hb_emb1p[M0 * PD176];      // emb1 padded
__device__ __half hb_emb2p[SRC * PD176];     // emb2 padded
__device__ __half hb_Wq[EQ*EQ];
__device__ __half hb_Wk[EQ*KDT];
__device__ __half hb_Wv[EQ*KDT];
__device__ __half hb_Wo[EQ*EQ];
__device__ __half hb_W1p[DDIM * PD448];
__device__ __half hb_W2p[DDIM * PD176];
// fp16 intermediates
__device__ __half hb_o0[M0*EQ];
__device__ __half hb_a0[M0*EQ];
__device__ __half hb_h0[M0*PD176];
__device__ __half hb_kvp1[M1*544];
__device__ __half hb_qp1 [M1*EQ];
__device__ __half hb_P  [2 * SRC * SRC];
__device__ __half hb_Vt [2 * HD * SRC];
__device__ __half hb_o1[M1*EQ];
__device__ __half hb_a1[M1*EQ];
__device__ __half hb_h1[M1*PD176];

// ---------------------------------------------------------------------------
// Fused fp32 -> fp16 convert + pack (one launch).
// Segments (float4 units of SOURCE data):
//  0 n0 pack   1 n1 pack   2 qin0 pack   3 emb1p   4 emb2p
//  5 Wq   6 Wk   7 Wv   8 Wo   9 W1p   10 W2p
// ---------------------------------------------------------------------------
struct CvtArgs {
    const float *emb0, *edge0, *td0, *emb1, *edge1, *td1, *emb2;
    const float *Wq, *Wk, *Wv, *Wo, *W1, *W2;
};

#define O0  0
#define O1  22732800
#define O2  25006080
#define O3  26398720
#define O4  27279360
#define O5  27367424
#define O6  27385920
#define O7  27687840
#define O8  27989760
#define O9  28008256
#define O10 28027348
#define O11 28034744

__device__ __forceinline__ uint2 pack4(const float* src) {
    float4 v = *reinterpret_cast<const float4*>(src);
    __half2 h0 = __float22half2_rn(make_float2(v.x, v.y));
    __half2 h1 = __float22half2_rn(make_float2(v.z, v.w));
    uint2 u;
    u.x = *reinterpret_cast<const uint32_t*>(&h0);
    u.y = *reinterpret_cast<const uint32_t*>(&h1);
    return u;
}

__global__ void __launch_bounds__(256)
cvt_all(CvtArgs a)
{
    const int stride = gridDim.x * blockDim.x;
    for (int i = blockIdx.x * blockDim.x + threadIdx.x; i < O11; i += stride) {
        if (i < O1) {                       // n0 pack
            int li = i;
            int row = li / 1110, f4 = li - row * 1110;
            int k = f4 * 4, n2 = f4 / 111, f = k - n2 * KD;
            size_t sub = (size_t)row * NB + n2;
            const float* s = (f < DDIM)   ? a.emb0  + sub * DDIM + f
                           : (f < 2*DDIM) ? a.edge0 + sub * EDIM + (f - DDIM)
                                          : a.td0   + sub * TDIM + (f - 2*DDIM);
            reinterpret_cast<uint2*>(hb_n0)[li] = pack4(s);
        } else if (i < O2) {                // n1 pack
            int li = i - O1;
            int row = li / 1110, f4 = li - row * 1110;
            int k = f4 * 4, n2 = f4 / 111, f = k - n2 * KD;
            size_t sub = (size_t)row * NB + n2;
            const float* s = (f < DDIM)   ? a.emb1  + sub * DDIM + f
                           : (f < 2*DDIM) ? a.edge1 + sub * EDIM + (f - DDIM)
                                          : a.td1   + sub * TDIM + (f - 2*DDIM);
            reinterpret_cast<uint2*>(hb_n1)[li] = pack4(s);
        } else if (i < O3) {                // qin0 pack
            int li = i - O2;
            int row = li / 68, c4 = li - row * 68;
            int k = c4 * 4;
            const float* s = (k < DDIM) ? a.emb1 + (size_t)row * DDIM + k
                                        : a.td1  + (size_t)row * TDIM + (k - DDIM);
            reinterpret_cast<uint2*>(hb_qin0)[li] = pack4(s);
        } else if (i < O4) {                // emb1p
            int li = i - O3;
            int row = li / 43, c4 = li - row * 43;
            reinterpret_cast<uint2*>(hb_emb1p)[row * 44 + c4] =
                pack4(a.emb1 + (size_t)row * DDIM + c4 * 4);
        } else if (i < O5) {                // emb2p
            int li = i - O4;
            int row = li / 43, c4 = li - row * 43;
            reinterpret_cast<uint2*>(hb_emb2p)[row * 44 + c4] =
                pack4(a.emb2 + (size_t)row * DDIM + c4 * 4);
        } else if (i < O6) {                // Wq dense
            int li = i - O5;
            reinterpret_cast<uint2*>(hb_Wq)[li] = pack4(a.Wq + (size_t)li * 4);
        } else if (i < O7) {                // Wk dense
            int li = i - O6;
            reinterpret_cast<uint2*>(hb_Wk)[li] = pack4(a.Wk + (size_t)li * 4);
        } else if (i < O8) {                // Wv dense
            int li = i - O7;
            reinterpret_cast<uint2*>(hb_Wv)[li] = pack4(a.Wv + (size_t)li * 4);
        } else if (i < O9) {                // Wo dense
            int li = i - O8;
            reinterpret_cast<uint2*>(hb_Wo)[li] = pack4(a.Wo + (size_t)li * 4);
        } else if (i < O10) {               // W1p
            int li = i - O9;
            int row = li / 111, c4 = li - row * 111;
            reinterpret_cast<uint2*>(hb_W1p)[row * 112 + c4] =
                pack4(a.W1 + (size_t)row * KD + c4 * 4);
        } else {                            // W2p
            int li = i - O10;
            int row = li / 43, c4 = li - row * 43;
            reinterpret_cast<uint2*>(hb_W2p)[row * 44 + c4] =
                pack4(a.W2 + (size_t)row * DDIM + c4 * 4);
        }
    }
}

// ---------------------------------------------------------------------------
// A/B address functors.
//   AMODE 0: dense A0[row*lda + k]
//   AMODE 3: concat a(272, lda=272) | b(172, padded ld=176)
//   BMODE 0: dense; BMODE 1: Wk|Wv split at n=272, ldb=KDT
// ---------------------------------------------------------------------------
template<int MODE>
__device__ __forceinline__ const __half* addrA(const __half* __restrict__ A0,
                                               const __half* __restrict__ A1,
                                               int lda, int row, int k)
{
    if (MODE == 0) return A0 + (size_t)row * lda + k;
    if (k < EQ)    return A0 + (size_t)row * EQ + k;
    return A1 + (size_t)row * PD176 + (k - EQ);
}

template<int MODE>
__device__ __forceinline__ const __half* addrB(const __half* __restrict__ B0,
                                               const __half* __restrict__ B1,
                                               int ldb, int n, int k)
{
    if (MODE == 0) return B0 + (size_t)n * ldb + k;
    if (n < EQ)    return B0 + (size_t)n * KDT + k;
    return B1 + (size_t)(n - EQ) * KDT + k;
}

// ---------------------------------------------------------------------------
// PTX helpers
// ---------------------------------------------------------------------------
__device__ __forceinline__ uint32_t smem_u32(const void* p) {
    uint32_t a;
    asm("{ .reg .u64 t; cvta.to.shared.u64 t, %1; cvt.u32.u64 %0, t; }"
        : "=r"(a) : "l"(p));
    return a;
}

// 16B cp.async.cg with zero-fill for src_bytes < 16
__device__ __forceinline__ void cp_async16(uint32_t smem, const void* gmem,
                                           int src_bytes) {
    asm volatile("cp.async.cg.shared.global [%0], [%1], 16, %2;"
                 :: "r"(smem), "l"(gmem), "r"(src_bytes));
}
#define CP_COMMIT() asm volatile("cp.async.commit_group;")
#define CP_WAIT2()  asm volatile("cp.async.wait_group 2;")

__device__ __forceinline__ void ldsm_x4(uint32_t r[4], uint32_t addr) {
    asm volatile("ldmatrix.sync.aligned.m8n8.x4.shared.b16 {%0,%1,%2,%3}, [%4];"
        : "=r"(r[0]), "=r"(r[1]), "=r"(r[2]), "=r"(r[3]) : "r"(addr));
}

__device__ __forceinline__ void mma_f16(float c[4], const uint32_t a[4],
                                        uint32_t b0, uint32_t b1) {
    asm volatile(
        "mma.sync.aligned.m16n8k16.row.col.f32.f16.f16.f32 "
        "{%0,%1,%2,%3}, {%4,%5,%6,%7}, {%8,%9}, {%0,%1,%2,%3};"
        : "+f"(c[0]), "+f"(c[1]), "+f"(c[2]), "+f"(c[3])
        : "r"(a[0]), "r"(a[1]), "r"(a[2]), "r"(a[3]), "r"(b0), "r"(b1));
}

// ---------------------------------------------------------------------------
// mma.sync fp16 GEMM, 4-stage cp.async.cg(16B) pipeline + ldmatrix.
// CTA tile 128x64xBK32, 256 threads (8 warps, 4x2), warp tile 32x32.
// Requires: row strides of all operands 16B-aligned (padded); concat
// boundary at 272 (%8==0); K-tails via cp.async zfill.
// ---------------------------------------------------------------------------
#define STAGES  4
#define ROWB    80
#define A_STG   10240
#define B_STG   5120
#define B_OFF   (STAGES * A_STG)
#define GM_SMEM (B_OFF + STAGES * B_STG)   // 61440

template<int AMODE, int BMODE, bool RELU, bool OUT16>
__global__ void __launch_bounds__(256)
gemm_mma(const __half* __restrict__ A0, const __half* __restrict__ A1,
         int lda,
         const __half* __restrict__ B0, const __half* __restrict__ B1, int ldb,
         const float* __restrict__ bias0, const float* __restrict__ bias1,
         void* __restrict__ Cv, int M, int N, int K, int ldc, float alpha)
{
    extern __shared__ char sh[];
    const uint32_t sbase = smem_u32(sh);

    const int tid  = threadIdx.x;
    const int wid  = tid >> 5;
    const int lane = tid & 31;
    const int g    = lane >> 2;
    const int t    = lane & 3;
    const int wm   = wid & 3;
    const int wn   = wid >> 2;
    const int m0   = blockIdx.y * 128;
    const int n0   = blockIdx.x * 64;

    const uint32_t a_lm = (uint32_t)(wm * 32 + (lane & 7) + ((lane >> 3) & 1) * 8) * ROWB
                        + ((lane >> 4) & 1) * 16;
    const uint32_t b_lm = (uint32_t)(wn * 32 + (lane & 7) + ((lane >> 4) & 1) * 8) * ROWB
                        + ((lane >> 3) & 1) * 16;

    float acc[2][4][4];
#pragma unroll
    for (int i = 0; i < 2; i++)
#pragma unroll
        for (int j = 0; j < 4; j++)
#pragma unroll
            for (int l = 0; l < 4; l++) acc[i][j][l] = 0.f;

    // staging: 16B chunks; thread -> (row 0..63, chunk 0..3)
    const int sr = tid >> 2;
    const int sc = tid & 3;
    const int KT = (K + 31) / 32;

#define ISSUE(st_, k0_)                                                        \
    do {                                                                       \
        const uint32_t abase = sbase + (st_) * A_STG;                          \
        const uint32_t bbase = sbase + B_OFF + (st_) * B_STG;                  \
        const int gk = (k0_) + sc * 8;                                         \
        int bk = (K - gk) * 2;                                                 \
        bk = bk < 0 ? 0 : (bk > 16 ? 16 : bk);                                 \
        const int gks = bk ? gk : 0;                                           \
        _Pragma("unroll")                                                      \
        for (int p = 0; p < 2; p++) {                                          \
            int r = sr + p * 64;                                               \
            const __half* src = addrA<AMODE>(A0, A1, lda, m0 + r, gks);        \
            cp_async16(abase + r * ROWB + sc * 16, src, bk);                   \
        }                                                                      \
        {                                                                      \
            int gn = n0 + sr;                                                  \
            int bb = (gn < N) ? bk : 0;                                        \
            const __half* src = addrB<BMODE>(B0, B1, ldb, bb ? gn : 0, gks);   \
            cp_async16(bbase + sr * ROWB + sc * 16, src, bb);                  \
        }                                                                      \
    } while (0)

    ISSUE(0, 0);  CP_COMMIT();
    ISSUE(1, 32); CP_COMMIT();
    ISSUE(2, 64); CP_COMMIT();
    CP_WAIT2();
    __syncthreads();

    int st = 0;
    for (int it = 0; it < KT; ++it) {
        int st3 = st + 3; if (st3 >= STAGES) st3 -= STAGES;
        if (it + 3 < KT) ISSUE(st3, (it + 3) * 32);
        CP_COMMIT();

        const uint32_t Abu = sbase + st * A_STG + a_lm;
        const uint32_t Bbu = sbase + B_OFF + st * B_STG + b_lm;
#pragma unroll
        for (int ks = 0; ks < 2; ks++) {
            uint32_t af[2][4], bq[2][4];
#pragma unroll
            for (int mt = 0; mt < 2; mt++)
                ldsm_x4(af[mt], Abu + mt * (16 * ROWB) + ks * 32);
#pragma unroll
            for (int ntp = 0; ntp < 2; ntp++)
                ldsm_x4(bq[ntp], Bbu + ntp * (16 * ROWB) + ks * 32);
#pragma unroll
            for (int mt = 0; mt < 2; mt++)
#pragma unroll
                for (int ntp = 0; ntp < 2; ntp++) {
                    mma_f16(acc[mt][2*ntp + 0], af[mt], bq[ntp][0], bq[ntp][1]);
                    mma_f16(acc[mt][2*ntp + 1], af[mt], bq[ntp][2], bq[ntp][3]);
                }
        }

        CP_WAIT2();
        __syncthreads();
        if (++st >= STAGES) st = 0;
    }

#pragma unroll
    for (int mt = 0; mt < 2; mt++) {
        int row0 = m0 + wm * 32 + mt * 16 + g;
#pragma unroll
        for (int nt = 0; nt < 4; nt++) {
            int col = n0 + wn * 32 + nt * 8 + t * 2;
#pragma unroll
            for (int half_ = 0; half_ < 2; half_++) {
                int gm = row0 + half_ * 8;
                if (gm >= M) continue;
#pragma unroll
                for (int cc = 0; cc < 2; cc++) {
                    int gn = col + cc;
                    if (gn >= N) continue;
                    float bval = (BMODE == 1)
                               ? (gn < EQ ? bias0[gn] : bias1[gn - EQ])
                               : bias0[gn];
                    float v = (acc[mt][nt][half_ * 2 + cc] + bval) * alpha;
                    if (RELU) v = fmaxf(v, 0.f);
                    if (OUT16)
                        ((__half*)Cv)[(size_t)gm * ldc + gn] = __float2half(v);
                    else
                        ((float*)Cv)[(size_t)gm * ldc + gn] = v;
                }
            }
        }
    }
#undef ISSUE
}

// ---------------------------------------------------------------------------
// Attention prop0: per node, 2 heads, 10x10, hd=136.  Emits fp16 o.
// ---------------------------------------------------------------------------
__global__ void __launch_bounds__(256)
attn0_kernel(const float* __restrict__ qp, const float* __restrict__ kvp,
             __half* __restrict__ o)
{
    __shared__ float Qs[NB][EQ];
    __shared__ float Ks[NB][EQ];
    __shared__ float Vs[NB][EQ];
    __shared__ float P[2][NB][NB];

    const int s = blockIdx.x;
    const int tid = threadIdx.x;
    const size_t base = (size_t)s * NB;

    for (int i = tid; i < NB * EQ; i += 256) {
        int r = i / EQ, f = i - r * EQ;
        Qs[r][f] = qp[(base + r) * EQ + f];
        Ks[r][f] = kvp[(base + r) * 544 + f];
        Vs[r][f] = kvp[(base + r) * 544 + EQ + f];
    }
    __syncthreads();

    if (tid < 200) {
        int h = tid / 100, rem = tid - h * 100;
        int qi = rem / NB, ki = rem - qi * NB;
        const float* q = &Qs[qi][h * HD];
        const float* k = &Ks[ki][h * HD];
        float acc = 0.f;
#pragma unroll 8
        for (int d = 0; d < HD; d++) acc = fmaf(q[d], k[d], acc);
        P[h][qi][ki] = acc;
    }
    __syncthreads();

    if (tid < 20) {
        int h = tid / NB, qi = tid - h * NB;
        float mx = -1e30f;
#pragma unroll
        for (int ki = 0; ki < NB; ki++) mx = fmaxf(mx, P[h][qi][ki]);
        float sum = 0.f;
#pragma unroll
        for (int ki = 0; ki < NB; ki++) {
            float e = expf(P[h][qi][ki] - mx);
            P[h][qi][ki] = e;
            sum += e;
        }
        float inv = 1.f / sum;
#pragma unroll
        for (int ki = 0; ki < NB; ki++) P[h][qi][ki] *= inv;
    }
    __syncthreads();

    for (int i = tid; i < NB * EQ; i += 256) {
        int qi = i / EQ, f = i - qi * EQ;
        int h = f / HD;
        float acc = 0.f;
#pragma unroll
        for (int ki = 0; ki < NB; ki++) acc = fmaf(P[h][qi][ki], Vs[ki][f], acc);
        o[(base + qi) * EQ + f] = __float2half(acc);
    }
}

// ---------------------------------------------------------------------------
// prop1 attention helpers
// ---------------------------------------------------------------------------
__global__ void __launch_bounds__(256)
softmax_kernel(const float* __restrict__ S, __half* __restrict__ P)
{
    const int q = blockIdx.x;
    const int h = blockIdx.y;
    const float* srow = S + ((size_t)h * SRC + q) * SRC;
    __half* prow = P + ((size_t)h * SRC + q) * SRC;
    __shared__ float red[256];
    const int tid = threadIdx.x;

    float v[8];
#pragma unroll
    for (int j = 0; j < 8; j++) v[j] = srow[tid + j * 256];

    float mx = -1e30f;
#pragma unroll
    for (int j = 0; j < 8; j++) mx = fmaxf(mx, v[j]);
    red[tid] = mx; __syncthreads();
    for (int w = 128; w > 0; w >>= 1) {
        if (tid < w) red[tid] = fmaxf(red[tid], red[tid + w]);
        __syncthreads();
    }
    mx = red[0]; __syncthreads();

    float sum = 0.f;
#pragma unroll
    for (int j = 0; j < 8; j++) { v[j] = expf(v[j] - mx); sum += v[j]; }
    red[tid] = sum; __syncthreads();
    for (int w = 128; w > 0; w >>= 1) {
        if (tid < w) red[tid] += red[tid + w];
        __syncthreads();
    }
    float inv = 1.f / red[0];
#pragma unroll
    for (int j = 0; j < 8; j++)
        prow[tid + j * 256] = __float2half(v[j] * inv);
}

__global__ void __launch_bounds__(256)
vt_kernel(const __half* __restrict__ kv, __half* __restrict__ vt)
{
    int i = blockIdx.x * 256 + threadIdx.x;
    if (i < 2 * HD * SRC) {
        int key = i & (SRC - 1);
        int r   = i >> 11;
        vt[i] = kv[(size_t)key * 544 + EQ + r];
    }
}

// ---------------------------------------------------------------------------
// Host launch
// ---------------------------------------------------------------------------
extern "C" void kernel_launch(void* const* d_in, const int* in_sizes, int n_in,
                              void* d_out, int out_size)
{
    const float* emb0  = (const float*)d_in[0];
    const float* edge0 = (const float*)d_in[1];
    const float* td0   = (const float*)d_in[2];
    const float* emb1  = (const float*)d_in[3];
    const float* edge1 = (const float*)d_in[4];
    const float* td1   = (const float*)d_in[5];
    const float* emb2  = (const float*)d_in[6];
    const float* Wq    = (const float*)d_in[7];
    const float* bq    = (const float*)d_in[8];
    const float* Wk    = (const float*)d_in[9];
    const float* bk    = (const float*)d_in[10];
    const float* Wv    = (const float*)d_in[11];
    const float* bv    = (const float*)d_in[12];
    const float* Wo    = (const float*)d_in[13];
    const float* bo    = (const float*)d_in[14];
    const float* W1    = (const float*)d_in[15];
    const float* b1    = (const float*)d_in[16];
    const float* W2    = (const float*)d_in[17];
    const float* b2    = (const float*)d_in[18];
    float* out = (float*)d_out;

    float *kvp0, *qp0, *Sb, *zb;
    cudaGetSymbolAddress((void**)&kvp0, g_kvp0);
    cudaGetSymbolAddress((void**)&qp0,  g_qp0);
    cudaGetSymbolAddress((void**)&Sb,   g_S);
    cudaGetSymbolAddress((void**)&zb,   g_zb);

    __half *hn0, *hn1, *hqin0, *he1p, *he2p;
    __half *hWq, *hWk, *hWv, *hWo, *hW1p, *hW2p;
    __half *ho0, *ha0, *hh0, *ho1, *ha1, *hh1;
    __half *hkv1, *hq1, *hP, *hVt;
    cudaGetSymbolAddress((void**)&hn0,  hb_n0);
    cudaGetSymbolAddress((void**)&hn1,  hb_n1);
    cudaGetSymbolAddress((void**)&hqin0, hb_qin0);
    cudaGetSymbolAddress((void**)&he1p, hb_emb1p);
    cudaGetSymbolAddress((void**)&he2p, hb_emb2p);
    cudaGetSymbolAddress((void**)&hWq, hb_Wq);
    cudaGetSymbolAddress((void**)&hWk, hb_Wk);
    cudaGetSymbolAddress((void**)&hWv, hb_Wv);
    cudaGetSymbolAddress((void**)&hWo, hb_Wo);
    cudaGetSymbolAddress((void**)&hW1p, hb_W1p);
    cudaGetSymbolAddress((void**)&hW2p, hb_W2p);
    cudaGetSymbolAddress((void**)&ho0, hb_o0);
    cudaGetSymbolAddress((void**)&ha0, hb_a0);
    cudaGetSymbolAddress((void**)&hh0, hb_h0);
    cudaGetSymbolAddress((void**)&ho1, hb_o1);
    cudaGetSymbolAddress((void**)&ha1, hb_a1);
    cudaGetSymbolAddress((void**)&hh1, hb_h1);
    cudaGetSymbolAddress((void**)&hkv1, hb_kvp1);
    cudaGetSymbolAddress((void**)&hq1,  hb_qp1);
    cudaGetSymbolAddress((void**)&hP,   hb_P);
    cudaGetSymbolAddress((void**)&hVt,  hb_Vt);

    static cudaStream_t s2 = nullptr;
    static cudaEvent_t evFork = nullptr, evJoin = nullptr;
    if (s2 == nullptr) {
        cudaStreamCreateWithFlags(&s2, cudaStreamNonBlocking);
        cudaEventCreateWithFlags(&evFork, cudaEventDisableTiming);
        cudaEventCreateWithFlags(&evJoin, cudaEventDisableTiming);
    }
    cudaStream_t s0 = (cudaStream_t)0;

    const float scale = 1.0f / sqrtf((float)HD);
    cudaFuncSetAttribute(gemm_mma<0, 1, false, false>,
                         cudaFuncAttributeMaxDynamicSharedMemorySize, GM_SMEM);
    cudaFuncSetAttribute(gemm_mma<0, 1, false, true>,
                         cudaFuncAttributeMaxDynamicSharedMemorySize, GM_SMEM);
    cudaFuncSetAttribute(gemm_mma<0, 0, false, true>,
                         cudaFuncAttributeMaxDynamicSharedMemorySize, GM_SMEM);
    cudaFuncSetAttribute(gemm_mma<3, 0, true, true>,
                         cudaFuncAttributeMaxDynamicSharedMemorySize, GM_SMEM);
    cudaFuncSetAttribute(gemm_mma<0, 0, false, false>,
                         cudaFuncAttributeMaxDynamicSharedMemorySize, GM_SMEM);

    // ---------------- fused convert + pack (single launch) -------------
    CvtArgs ca;
    ca.emb0 = emb0; ca.edge0 = edge0; ca.td0 = td0;
    ca.emb1 = emb1; ca.edge1 = edge1; ca.td1 = td1;
    ca.emb2 = emb2;
    ca.Wq = Wq; ca.Wk = Wk; ca.Wv = Wv; ca.Wo = Wo; ca.W1 = W1; ca.W2 = W2;
    cvt_all<<<4736, 256, 0, s0>>>(ca);

    // ---------------- fork ----------------
    cudaEventRecord(evFork, s0);
    cudaStreamWaitEvent(s2, evFork, 0);

    // ---------------- propagation 1 + passthrough (side stream) ---------
    cudaMemcpyAsync(out + OUT_EDGE, edge1,
                    (size_t)SRC * NB * EDIM * sizeof(float),
                    cudaMemcpyDeviceToDevice, s2);
    cudaMemcpyAsync(out + OUT_TD, td1,
                    (size_t)SRC * NB * TDIM * sizeof(float),
                    cudaMemcpyDeviceToDevice, s2);
    gemm_mma<0, 1, false, true><<<dim3(9, 16), 256, GM_SMEM, s2>>>(
        hn1, nullptr, KDT, hWk, hWv, KDT, bk, bv,
        hkv1, M1, 544, KDT, 544, 1.f);
    gemm_mma<0, 0, false, true><<<dim3(5, 16), 256, GM_SMEM, s2>>>(
        he2p, nullptr, PD176, hWq, nullptr, EQ, bq, nullptr,
        hq1, M1, EQ, DDIM, EQ, scale);
    vt_kernel<<<(2 * HD * SRC + 255) / 256, 256, 0, s2>>>(hkv1, hVt);
    for (int h = 0; h < 2; h++) {
        gemm_mma<0, 0, false, false><<<dim3(32, 16), 256, GM_SMEM, s2>>>(
            hq1 + h * HD, nullptr, EQ,
            hkv1 + h * HD, nullptr, 544, zb, nullptr,
            Sb + (size_t)h * SRC * SRC, SRC, SRC, HD, SRC, 1.f);
    }
    softmax_kernel<<<dim3(SRC, 2), 256, 0, s2>>>(Sb, hP);
    for (int h = 0; h < 2; h++) {
        gemm_mma<0, 0, false, true><<<dim3(3, 16), 256, GM_SMEM, s2>>>(
            hP + (size_t)h * SRC * SRC, nullptr, SRC,
            hVt + (size_t)h * HD * SRC, nullptr, SRC, zb, nullptr,
            ho1 + h * HD, SRC, HD, SRC, EQ, 1.f);
    }
    gemm_mma<0, 0, false, true><<<dim3(5, 16), 256, GM_SMEM, s2>>>(
        ho1, nullptr, EQ, hWo, nullptr, EQ, bo, nullptr,
        ha1, M1, EQ, EQ, EQ, 1.f);
    gemm_mma<3, 0, true, true><<<dim3(3, 16), 256, GM_SMEM, s2>>>(
        ha1, he2p, 0, hW1p, nullptr, PD448, b1, nullptr,
        hh1, M1, DDIM, KD, PD176, 1.f);
    gemm_mma<0, 0, false, false><<<dim3(3, 16), 256, GM_SMEM, s2>>>(
        hh1, nullptr, PD176, hW2p, nullptr, PD176, b2, nullptr,
        out + OUT_R1, M1, DDIM, DDIM, DDIM, 1.f);
    cudaEventRecord(evJoin, s2);

    // ---------------- propagation 0 (main stream) ----------------
    gemm_mma<0, 1, false, false><<<dim3(9, 160), 256, GM_SMEM, s0>>>(
        hn0, nullptr, KDT, hWk, hWv, KDT, bk, bv,
        kvp0, M0, 544, KDT, 544, 1.f);
    gemm_mma<0, 0, false, false><<<dim3(5, 160), 256, GM_SMEM, s0>>>(
        hqin0, nullptr, EQ, hWq, nullptr, EQ, bq, nullptr,
        qp0, M0, EQ, EQ, EQ, scale);
    attn0_kernel<<<SRC, 256, 0, s0>>>(qp0, kvp0, ho0);
    gemm_mma<0, 0, false, true><<<dim3(5, 160), 256, GM_SMEM, s0>>>(
        ho0, nullptr, EQ, hWo, nullptr, EQ, bo, nullptr,
        ha0, M0, EQ, EQ, EQ, 1.f);
    gemm_mma<3, 0, true, true><<<dim3(3, 160), 256, GM_SMEM, s0>>>(
        ha0, he1p, 0, hW1p, nullptr, PD448, b1, nullptr,
        hh0, M0, DDIM, KD, PD176, 1.f);
    gemm_mma<0, 0, false, false><<<dim3(3, 160), 256, GM_SMEM, s0>>>(
        hh0, nullptr, PD176, hW2p, nullptr, PD176, b2, nullptr,
        out + OUT_R0, M0, DDIM, DDIM, DDIM, 1.f);

    // ---------------- join ----------------
    cudaStreamWaitEvent(s0, evJoin, 0);
}